// round 5
// baseline (speedup 1.0000x reference)
#include <cuda_runtime.h>
#include <cuda_fp16.h>
#include <cooperative_groups.h>
#include <math.h>

namespace cg = cooperative_groups;

// ============================================================================
// DGISubgraphCL — 7-launch pipeline: dual-CSR build + fp16 feat, fused pos/neg
// GCN, concurrent dual frontier-BFS + exact top-k, fused masked GCN, loss.
// ============================================================================

#define N_MAX 131072
#define E_MAX (N_MAX * 17)
#define HIST_BINS 15001
#define CSRB 264         // csr kernel blocks (2/SM)
#define BFSB 132         // bfs kernel blocks (1/SM)
#define GB 66            // blocks per BFS group (2 groups)
#define MAX_SWEEPS 250   // round-3 evidence: <=16 sweeps suffice

// ---- device scratch ----
__device__ int g_rowD[N_MAX + 1], g_cntD[N_MAX], g_curD[N_MAX];
__device__ int g_rowS[N_MAX + 1], g_cntS[N_MAX], g_curS[N_MAX];
__device__ int g_colD[E_MAX];
__device__ int g_colS[E_MAX];
__device__ __half g_feat16[(size_t)N_MAX * 64];
__device__ int g_hopG[2][N_MAX];
__device__ int g_front[2][2][N_MAX];
__device__ int g_invpermG[2][N_MAX];
__device__ int g_histG[2][HIST_BINS];
__device__ int g_szHist[2][MAX_SWEEPS + 8];
__device__ unsigned char g_keep1[N_MAX];
__device__ unsigned char g_keep2[N_MAX];
__device__ float g_hpos[(size_t)N_MAX * 64];
__device__ float g_hneg[(size_t)N_MAX * 64];
__device__ double g_summary[128];
__device__ float g_v[2][64];
__device__ double g_loss[4];

__device__ int g_bsD[CSRB], g_bsS[CSRB], g_offD[CSRB], g_offS[CSRB];
__device__ int g_blkCntG[2][GB];
__device__ unsigned long long g_seedkeyG[2];
__device__ int g_hstarG[2], g_rremG[2], g_pstarG[2], g_pselBlockG[2], g_pselRemG[2];

// software barriers (monotonic counters, reset at kernel exit)
__device__ unsigned g_barC = 0;
__device__ unsigned g_barG[2] = {0, 0};

// ============================================================================
// helpers
// ============================================================================

__device__ __forceinline__ void xsync(unsigned* ctr, unsigned nblk, unsigned& epoch) {
    __syncthreads();
    if (threadIdx.x == 0) {
        __threadfence();
        unsigned target = (epoch + 1) * nblk;
        atomicAdd(ctr, 1u);
        while (*((volatile unsigned*)ctr) < target) {}
        __threadfence();
    }
    epoch++;
    __syncthreads();
}

__device__ __forceinline__ void xexit(unsigned* ctr, unsigned nblk, unsigned epoch) {
    __syncthreads();
    if (threadIdx.x == 0) {
        __threadfence();
        unsigned target = (epoch + 1) * nblk;
        if (atomicAdd(ctr, 1u) + 1 == target) *ctr = 0;
    }
}

__device__ __forceinline__ float softplusf(float x) {
    return fmaxf(x, 0.f) + log1pf(expf(-fabsf(x)));
}

__device__ __forceinline__ unsigned long long ullmin2(unsigned long long a, unsigned long long b) {
    return a < b ? a : b;
}

// inclusive block scan, blockDim.x == 1024 required
__device__ __forceinline__ int blockScanInc(int v, int* sWarp) {
    int lane = threadIdx.x & 31;
    int wid = threadIdx.x >> 5;
#pragma unroll
    for (int off = 1; off < 32; off <<= 1) {
        int t = __shfl_up_sync(0xffffffffu, v, off);
        if (lane >= off) v += t;
    }
    if (lane == 31) sWarp[wid] = v;
    __syncthreads();
    if (wid == 0) {
        int w = sWarp[lane];
#pragma unroll
        for (int off = 1; off < 32; off <<= 1) {
            int t = __shfl_up_sync(0xffffffffu, w, off);
            if (lane >= off) w += t;
        }
        sWarp[lane] = w;
    }
    __syncthreads();
    return v + (wid ? sWarp[wid - 1] : 0);
}

// ============================================================================
// Kernel 1: dual CSR build + feat->fp16 + zeroing
// ============================================================================

__global__ __launch_bounds__(1024, 2)
void csr_kernel(const float* __restrict__ feat, const int* __restrict__ src,
                const int* __restrict__ dst, int e, int n) {
    unsigned epoch = 0;
    int gtid = blockIdx.x * 1024 + threadIdx.x;
    int gsz = gridDim.x * 1024;

    // phase 0: zero + fp16 convert
    for (int i = gtid; i < n; i += gsz) { g_cntD[i] = 0; g_cntS[i] = 0; g_curD[i] = 0; g_curS[i] = 0; }
    if (gtid < 4) g_loss[gtid] = 0.0;
    if (gtid < 128) g_summary[gtid] = 0.0;
    if (gtid == 0) { g_rowD[n] = e; g_rowS[n] = e; }
    {
        int tot = n * 32;  // float2 units
        const float2* f2 = reinterpret_cast<const float2*>(feat);
        __half2* h2 = reinterpret_cast<__half2*>(g_feat16);
        for (int i = gtid; i < tot; i += gsz) h2[i] = __float22half2_rn(f2[i]);
    }
    xsync(&g_barC, gridDim.x, epoch);

    // phase 1: count degrees (both directions)
    for (int i = gtid; i < e; i += gsz) {
        atomicAdd(&g_cntD[dst[i]], 1);
        atomicAdd(&g_cntS[src[i]], 1);
    }
    xsync(&g_barC, gridDim.x, epoch);

    // phase 2: per-block exclusive scans for both CSRs
    __shared__ int sWarp[32];
    __shared__ int sRun, sTot;
    int chunk = (n + gridDim.x - 1) / gridDim.x;
    int b0 = blockIdx.x * chunk;
    int b1 = min(b0 + chunk, n);
    for (int which = 0; which < 2; which++) {
        int* cnt = which ? g_cntS : g_cntD;
        int* row = which ? g_rowS : g_rowD;
        int* bs = which ? g_bsS : g_bsD;
        if (threadIdx.x == 0) sRun = 0;
        __syncthreads();
        for (int base = b0; base < b1; base += 1024) {
            int i = base + threadIdx.x;
            int v = (i < b1) ? __ldcg(&cnt[i]) : 0;
            int incl = blockScanInc(v, sWarp);
            if (i < b1) row[i] = sRun + incl - v;
            if (threadIdx.x == 1023) sTot = incl;
            __syncthreads();
            if (threadIdx.x == 0) sRun += sTot;
            __syncthreads();
        }
        if (threadIdx.x == 0) bs[blockIdx.x] = sRun;
        __syncthreads();
    }
    xsync(&g_barC, gridDim.x, epoch);

    // phase 3: block 0 scans block sums
    if (blockIdx.x == 0) {
        int b = threadIdx.x;
        int vD = (b < (int)gridDim.x) ? __ldcg(&g_bsD[b]) : 0;
        int incl = blockScanInc(vD, sWarp);
        if (b < (int)gridDim.x) g_offD[b] = incl - vD;
        int vS = (b < (int)gridDim.x) ? __ldcg(&g_bsS[b]) : 0;
        incl = blockScanInc(vS, sWarp);
        if (b < (int)gridDim.x) g_offS[b] = incl - vS;
    }
    xsync(&g_barC, gridDim.x, epoch);

    // phase 4: add offsets
    {
        int oD = __ldcg(&g_offD[blockIdx.x]);
        int oS = __ldcg(&g_offS[blockIdx.x]);
        for (int i = b0 + threadIdx.x; i < b1; i += 1024) {
            g_rowD[i] = __ldcg(&g_rowD[i]) + oD;
            g_rowS[i] = __ldcg(&g_rowS[i]) + oS;
        }
    }
    xsync(&g_barC, gridDim.x, epoch);

    // phase 5: scatter both
    for (int i = gtid; i < e; i += gsz) {
        int d = dst[i], s = src[i];
        int pd = atomicAdd(&g_curD[d], 1);
        g_colD[__ldcg(&g_rowD[d]) + pd] = s;
        int ps = atomicAdd(&g_curS[s], 1);
        g_colS[__ldcg(&g_rowS[s]) + ps] = d;
    }
    xexit(&g_barC, gridDim.x, epoch);
}

// ============================================================================
// Kernel 2: fused pos + neg GCN (fp16 gathers, fp32 math)
// ============================================================================

__global__ __launch_bounds__(256)
void gcn_fused_kernel(const float* __restrict__ Wenc, const int* __restrict__ permneg, int n) {
    __shared__ float sW[4096];
    __shared__ float sxp[8][64];
    __shared__ float sxn[8][64];
    int tid = threadIdx.x;
    for (int j = tid; j < 4096; j += 256) sW[j] = Wenc[j];
    __syncthreads();
    int warp = tid >> 5, lane = tid & 31;
    for (int node = blockIdx.x * 8 + warp; node < n; node += gridDim.x * 8) {
        int s0 = g_rowD[node], s1 = g_rowD[node + 1];
        float ap0 = 0.f, ap1 = 0.f, an0 = 0.f, an1 = 0.f;
#pragma unroll 2
        for (int e2 = s0; e2 < s1; e2++) {
            int s = g_colD[e2];
            int r = __ldg(&permneg[s]);
            float2 fp = __half22float2(*reinterpret_cast<const __half2*>(g_feat16 + (size_t)s * 64 + 2 * lane));
            float2 fn = __half22float2(*reinterpret_cast<const __half2*>(g_feat16 + (size_t)r * 64 + 2 * lane));
            ap0 += fp.x; ap1 += fp.y; an0 += fn.x; an1 += fn.y;
        }
        float invd = 1.f / (float)max(s1 - s0, 1);
        sxp[warp][2 * lane] = ap0 * invd; sxp[warp][2 * lane + 1] = ap1 * invd;
        sxn[warp][2 * lane] = an0 * invd; sxn[warp][2 * lane + 1] = an1 * invd;
        __syncwarp();
        float op0 = 0.f, op1 = 0.f, on0 = 0.f, on1 = 0.f;
#pragma unroll
        for (int kk = 0; kk < 64; kk++) {
            float w0 = sW[kk * 64 + 2 * lane], w1 = sW[kk * 64 + 2 * lane + 1];
            float xp = sxp[warp][kk], xn = sxn[warp][kk];
            op0 += xp * w0; op1 += xp * w1; on0 += xn * w0; on1 += xn * w1;
        }
        *reinterpret_cast<float2*>(g_hpos + (size_t)node * 64 + 2 * lane) =
            make_float2(fmaxf(op0, 0.f), fmaxf(op1, 0.f));
        *reinterpret_cast<float2*>(g_hneg + (size_t)node * 64 + 2 * lane) =
            make_float2(fmaxf(on0, 0.f), fmaxf(on1, 0.f));
        __syncwarp();
    }
}

// ============================================================================
// Kernel 3: dual frontier-BFS + exact top-k selection (both perms concurrent)
// ============================================================================

__global__ __launch_bounds__(1024, 1)
void bfs_dual_kernel(const int* __restrict__ perm1, const int* __restrict__ perm2, int n, int k) {
    int g = (blockIdx.x < GB) ? 0 : 1;
    int gb = blockIdx.x - g * GB;
    const int* perm = g ? perm2 : perm1;
    unsigned char* keep = g ? g_keep2 : g_keep1;
    int* hop = g_hopG[g];
    int* invp = g_invpermG[g];
    int* hist = g_histG[g];
    unsigned* bar = &g_barG[g];
    unsigned epoch = 0;
    int gtid = gb * 1024 + threadIdx.x;
    int gsz = GB * 1024;
    const int INF = n;

    __shared__ int sWarp[32];
    __shared__ unsigned long long sK[32];

    // init
    int root = __ldg(&perm[0]);
    for (int i = gtid; i < n; i += gsz) {
        __stcg(&hop[i], (i == root) ? 0 : INF);
        __stcg(&invp[__ldg(&perm[i])], i);
    }
    for (int i = gtid; i < HIST_BINS; i += gsz) __stcg(&hist[i], 0);
    for (int i = gtid; i < MAX_SWEEPS + 8; i += gsz) __stcg(&g_szHist[g][i], 0);
    if (gtid == 0) {
        __stcg(&g_front[g][0][0], root);
        __stcg(&g_szHist[g][0], 1);
        g_seedkeyG[g] = ~0ull;
    }
    xsync(bar, GB, epoch);

    // frontier BFS (exact: sources only added when frontier empty, so hop
    // values never decrease after first assignment == synchronous relax)
    int cnt = 1;
    int t = 0;
    int lane = threadIdx.x & 31;
    while (cnt <= k && t < MAX_SWEEPS) {
        int fsz = __ldcg(&g_szHist[g][t]);
        const int* fin = g_front[g][t & 1];
        int* fout = g_front[g][(t + 1) & 1];
        int* ctr = &g_szHist[g][t + 1];
        for (int idx = gtid; idx < fsz; idx += gsz) {
            int u = __ldcg(&fin[idx]);
            int s0 = g_rowS[u], s1 = g_rowS[u + 1];
            for (int e2 = s0; e2 < s1; e2++) {
                int v = g_colS[e2];
                bool win = false;
                if (__ldcg(&hop[v]) == INF)
                    win = (atomicCAS(&hop[v], INF, t + 1) == INF);
                if (win) {
                    cg::coalesced_group grp = cg::coalesced_threads();
                    int base;
                    if (grp.thread_rank() == 0) base = atomicAdd(ctr, (int)grp.size());
                    base = grp.shfl(base, 0);
                    __stcg(&fout[base + grp.thread_rank()], v);
                }
            }
        }
        xsync(bar, GB, epoch);
        int newly = __ldcg(&g_szHist[g][t + 1]);
        t += 1;
        cnt += newly;
        if (newly == 0 && cnt <= k) {
            // stuck: seed unreached node with min perm at hop = t
            unsigned long long key = ~0ull;
            for (int i = gtid; i < n; i += gsz) {
                if (__ldcg(&hop[i]) == INF)
                    key = ullmin2(key, ((unsigned long long)(unsigned)__ldg(&perm[i]) << 32) | (unsigned)i);
            }
#pragma unroll
            for (int off = 16; off; off >>= 1)
                key = ullmin2(key, __shfl_down_sync(0xffffffffu, key, off));
            int wid = threadIdx.x >> 5;
            if (lane == 0) sK[wid] = key;
            __syncthreads();
            if (threadIdx.x < 32) {
                unsigned long long kk2 = sK[threadIdx.x];
#pragma unroll
                for (int off = 16; off; off >>= 1)
                    kk2 = ullmin2(kk2, __shfl_down_sync(0xffffffffu, kk2, off));
                if (threadIdx.x == 0 && kk2 != ~0ull) atomicMin(&g_seedkeyG[g], kk2);
            }
            xsync(bar, GB, epoch);
            if (gtid == 0) {
                unsigned long long kv = g_seedkeyG[g];
                int idx = (int)(unsigned)(kv & 0xffffffffull);
                __stcg(&hop[idx], t);
                __stcg(&g_front[g][t & 1][0], idx);
                __stcg(&g_szHist[g][t], 1);
                g_seedkeyG[g] = ~0ull;
            }
            cnt += 1;
            xsync(bar, GB, epoch);
        }
    }

    // histogram of clipped hops
    {
        __shared__ int sh[256];
        for (int j = threadIdx.x; j < 256; j += 1024) sh[j] = 0;
        __syncthreads();
        for (int i = gtid; i < n; i += gsz) {
            int hv = min(__ldcg(&hop[i]), 15000);
            if (hv < 256) atomicAdd(&sh[hv], 1);
            else atomicAdd(&hist[hv], 1);
        }
        __syncthreads();
        for (int j = threadIdx.x; j < 256; j += 1024)
            if (sh[j]) atomicAdd(&hist[j], sh[j]);
    }
    xsync(bar, GB, epoch);

    // hstar
    if (gb == 0) {
        __shared__ int sRun, sTot, sDone;
        if (threadIdx.x == 0) { sRun = 0; sDone = 0; }
        __syncthreads();
        for (int base = 0; base < HIST_BINS; base += 1024) {
            if (sDone) break;
            int h = base + threadIdx.x;
            int v = (h < HIST_BINS) ? __ldcg(&hist[h]) : 0;
            int incl = blockScanInc(v, sWarp);
            int P = sRun + incl;
            if (v > 0 && P >= k && P - v < k) { g_hstarG[g] = h; g_rremG[g] = k - (P - v); sDone = 1; }
            if (threadIdx.x == 1023) sTot = incl;
            __syncthreads();
            if (threadIdx.x == 0) sRun += sTot;
            __syncthreads();
        }
    }
    xsync(bar, GB, epoch);
    int hstar = *(volatile int*)&g_hstarG[g];
    int rrem = *(volatile int*)&g_rremG[g];

    // pstar: rrem-th smallest perm value among hop==hstar
    int chunk = (n + GB - 1) / GB;
    int v0 = gb * chunk, v1 = min(v0 + chunk, n);
    {
        int c = 0;
        for (int v = v0 + threadIdx.x; v < v1; v += 1024) {
            int j = __ldcg(&invp[v]);
            c += (min(__ldcg(&hop[j]), 15000) == hstar);
        }
#pragma unroll
        for (int off = 16; off; off >>= 1) c += __shfl_down_sync(0xffffffffu, c, off);
        int wid = threadIdx.x >> 5;
        if (lane == 0) sWarp[wid] = c;
        __syncthreads();
        if (threadIdx.x < 32) {
            int r = sWarp[threadIdx.x];
#pragma unroll
            for (int off = 16; off; off >>= 1) r += __shfl_down_sync(0xffffffffu, r, off);
            if (threadIdx.x == 0) g_blkCntG[g][gb] = r;
        }
    }
    xsync(bar, GB, epoch);
    if (gb == 0) {
        int b = threadIdx.x;
        int v = (b < GB) ? __ldcg(&g_blkCntG[g][b]) : 0;
        int incl = blockScanInc(v, sWarp);
        int excl = incl - v;
        if (b < GB && v > 0 && excl < rrem && rrem <= incl) {
            g_pselBlockG[g] = b; g_pselRemG[g] = rrem - excl;
        }
    }
    xsync(bar, GB, epoch);
    if (gb == *(volatile int*)&g_pselBlockG[g]) {
        int rem = *(volatile int*)&g_pselRemG[g];
        __shared__ int sRun2, sTot2, sDone2;
        if (threadIdx.x == 0) { sRun2 = 0; sDone2 = 0; }
        __syncthreads();
        for (int base = v0; base < v1; base += 1024) {
            if (sDone2) break;
            int v = base + threadIdx.x;
            int pred = 0;
            if (v < v1) {
                int j = __ldcg(&invp[v]);
                pred = (min(__ldcg(&hop[j]), 15000) == hstar);
            }
            int incl = blockScanInc(pred, sWarp);
            int cum = sRun2 + incl;
            if (pred && cum == rem) { g_pstarG[g] = v; sDone2 = 1; }
            if (threadIdx.x == 1023) sTot2 = incl;
            __syncthreads();
            if (threadIdx.x == 0) sRun2 += sTot2;
            __syncthreads();
        }
    }
    xsync(bar, GB, epoch);
    int pstar = *(volatile int*)&g_pstarG[g];
    for (int i = gtid; i < n; i += gsz) {
        int hv = min(__ldcg(&hop[i]), 15000);
        keep[i] = (hv < hstar) || (hv == hstar && __ldg(&perm[i]) <= pstar);
    }
    xexit(bar, GB, epoch);
}

// ============================================================================
// Kernel 4: fused masked GCN for BOTH perms (fp16 gathers, fp64 summary)
// ============================================================================

__global__ __launch_bounds__(256)
void masked_gcn_kernel(const float* __restrict__ Wenc, int n) {
    __shared__ float sW[4096];
    __shared__ float sx1[8][64];
    __shared__ float sx2[8][64];
    __shared__ double sSum[128];
    int tid = threadIdx.x;
    for (int j = tid; j < 4096; j += 256) sW[j] = Wenc[j];
    if (tid < 128) sSum[tid] = 0.0;
    __syncthreads();
    int warp = tid >> 5, lane = tid & 31;
    double a10 = 0.0, a11 = 0.0, a20 = 0.0, a21 = 0.0;
    for (int node = blockIdx.x * 8 + warp; node < n; node += gridDim.x * 8) {
        int k1d = g_keep1[node], k2d = g_keep2[node];
        if (!(k1d | k2d)) continue;
        int s0 = g_rowD[node], s1 = g_rowD[node + 1];
        float b10 = 0.f, b11 = 0.f, b20 = 0.f, b21 = 0.f;
        int c1 = 0, c2 = 0;
        for (int e2 = s0; e2 < s1; e2++) {
            int s = g_colD[e2];
            int k1 = k1d & (int)g_keep1[s];
            int k2 = k2d & (int)g_keep2[s];
            if (k1 | k2) {
                float2 f = __half22float2(*reinterpret_cast<const __half2*>(g_feat16 + (size_t)s * 64 + 2 * lane));
                if (k1) { b10 += f.x; b11 += f.y; c1++; }
                if (k2) { b20 += f.x; b21 += f.y; c2++; }
            }
        }
        if (k1d) {
            float inv1 = 1.f / (float)max(c1, 1);
            sx1[warp][2 * lane] = b10 * inv1; sx1[warp][2 * lane + 1] = b11 * inv1;
        }
        if (k2d) {
            float inv2 = 1.f / (float)max(c2, 1);
            sx2[warp][2 * lane] = b20 * inv2; sx2[warp][2 * lane + 1] = b21 * inv2;
        }
        __syncwarp();
        float o10 = 0.f, o11 = 0.f, o20 = 0.f, o21 = 0.f;
#pragma unroll
        for (int kk = 0; kk < 64; kk++) {
            float w0 = sW[kk * 64 + 2 * lane], w1 = sW[kk * 64 + 2 * lane + 1];
            if (k1d) { float x = sx1[warp][kk]; o10 += x * w0; o11 += x * w1; }
            if (k2d) { float x = sx2[warp][kk]; o20 += x * w0; o21 += x * w1; }
        }
        if (k1d) { a10 += (double)fmaxf(o10, 0.f); a11 += (double)fmaxf(o11, 0.f); }
        if (k2d) { a20 += (double)fmaxf(o20, 0.f); a21 += (double)fmaxf(o21, 0.f); }
        __syncwarp();
    }
    atomicAdd(&sSum[2 * lane], a10);
    atomicAdd(&sSum[2 * lane + 1], a11);
    atomicAdd(&sSum[64 + 2 * lane], a20);
    atomicAdd(&sSum[64 + 2 * lane + 1], a21);
    __syncthreads();
    if (tid < 128) {
        double v = sSum[tid];
        if (v != 0.0) atomicAdd(&g_summary[tid], v);
    }
}

// ============================================================================
// Kernel 5: v = W_disc @ sigmoid(summary/k) for both perms
// ============================================================================

__global__ void compute_v_kernel(const float* __restrict__ Wdisc, int k) {
    __shared__ float ss[2][64];
    int tid = threadIdx.x;  // 128 threads
    int p = tid >> 6, c = tid & 63;
    double s = g_summary[tid] / (double)k;
    ss[p][c] = (float)(1.0 / (1.0 + exp(-s)));
    __syncthreads();
    float v = 0.f;
#pragma unroll
    for (int b = 0; b < 64; b++) v += Wdisc[c * 64 + b] * ss[p][b];
    g_v[p][c] = v;
}

// ============================================================================
// Kernel 6: BCE losses for both perms in one pass over h_pos / h_neg
// ============================================================================

__global__ __launch_bounds__(256)
void loss_kernel(int n) {
    __shared__ float sv0[64], sv1[64];
    __shared__ double sL[4];
    int tid = threadIdx.x;
    if (tid < 64) { sv0[tid] = g_v[0][tid]; sv1[tid] = g_v[1][tid]; }
    if (tid < 4) sL[tid] = 0.0;
    __syncthreads();
    int warp = tid >> 5, lane = tid & 31;
    float v00 = sv0[2 * lane], v01 = sv0[2 * lane + 1];
    float v10 = sv1[2 * lane], v11 = sv1[2 * lane + 1];
    double l0 = 0, l1 = 0, l2 = 0, l3 = 0;
    for (int node = blockIdx.x * 8 + warp; node < n; node += gridDim.x * 8) {
        float2 hp = *reinterpret_cast<const float2*>(g_hpos + (size_t)node * 64 + 2 * lane);
        float2 hn = *reinterpret_cast<const float2*>(g_hneg + (size_t)node * 64 + 2 * lane);
        float p1 = hp.x * v00 + hp.y * v01;
        float p2 = hp.x * v10 + hp.y * v11;
        float q1 = hn.x * v00 + hn.y * v01;
        float q2 = hn.x * v10 + hn.y * v11;
#pragma unroll
        for (int off = 16; off; off >>= 1) {
            p1 += __shfl_down_sync(0xffffffffu, p1, off);
            p2 += __shfl_down_sync(0xffffffffu, p2, off);
            q1 += __shfl_down_sync(0xffffffffu, q1, off);
            q2 += __shfl_down_sync(0xffffffffu, q2, off);
        }
        if (lane == 0) {
            l0 += (double)softplusf(-p1);
            l1 += (double)softplusf(q1);
            l2 += (double)softplusf(-p2);
            l3 += (double)softplusf(q2);
        }
    }
    if (lane == 0) {
        atomicAdd(&sL[0], l0); atomicAdd(&sL[1], l1);
        atomicAdd(&sL[2], l2); atomicAdd(&sL[3], l3);
    }
    __syncthreads();
    if (tid < 4) atomicAdd(&g_loss[tid], sL[tid]);
}

__global__ void finalize_kernel(float* out, int n) {
    out[0] = (float)((g_loss[0] + g_loss[1] + g_loss[2] + g_loss[3]) / (double)n);
}

// ============================================================================
// launch
// ============================================================================

extern "C" void kernel_launch(void* const* d_in, const int* in_sizes, int n_in,
                              void* d_out, int out_size) {
    const float* feat = (const float*)d_in[0];
    const float* Wenc = (const float*)d_in[1];
    const float* Wdisc = (const float*)d_in[2];
    const int* src = (const int*)d_in[3];
    const int* dst = (const int*)d_in[4];
    const int* permneg = (const int*)d_in[5];
    const int* perm1 = (const int*)d_in[6];
    const int* perm2 = (const int*)d_in[7];

    int e = in_sizes[3];
    int n = in_sizes[5];
    int k = (int)((double)n * 0.8);

    csr_kernel<<<CSRB, 1024>>>(feat, src, dst, e, n);

    int gB = (n + 7) / 8;
    int gGrid = gB < 2960 ? gB : 2960;
    gcn_fused_kernel<<<gGrid, 256>>>(Wenc, permneg, n);

    bfs_dual_kernel<<<BFSB, 1024>>>(perm1, perm2, n, k);

    masked_gcn_kernel<<<gGrid, 256>>>(Wenc, n);
    compute_v_kernel<<<1, 128>>>(Wdisc, k);
    loss_kernel<<<gGrid, 256>>>(n);
    finalize_kernel<<<1, 1>>>((float*)d_out, n);
}

// round 6
// speedup vs baseline: 1.0544x; 1.0544x over previous
#include <cuda_runtime.h>
#include <cuda_fp16.h>
#include <cooperative_groups.h>
#include <math.h>

namespace cg = cooperative_groups;

// ============================================================================
// DGISubgraphCL — 6-launch pipeline:
//   csr (dual CSR + fp16 feat) -> dual frontier-BFS + top-k -> masked GCN
//   (4-node tiled GEMV, both perms) -> v -> fused pos/neg GCN + BCE loss.
// ============================================================================

#define N_MAX 131072
#define E_MAX (N_MAX * 17)
#define HIST_BINS 15001
#define CSRB 264
#define BFSB 132
#define GB 66
#define MAX_SWEEPS 250

// ---- device scratch ----
__device__ int g_rowD[N_MAX + 1], g_cntD[N_MAX], g_curD[N_MAX];
__device__ int g_rowS[N_MAX + 1], g_cntS[N_MAX], g_curS[N_MAX];
__device__ int g_colD[E_MAX];
__device__ int g_colS[E_MAX];
__device__ __half g_feat16[(size_t)N_MAX * 64];
__device__ int g_hopG[2][N_MAX];
__device__ int g_front[2][2][N_MAX];
__device__ int g_invpermG[2][N_MAX];
__device__ int g_histG[2][HIST_BINS];
__device__ int g_szHist[2][MAX_SWEEPS + 8];
__device__ unsigned char g_keep1[N_MAX];
__device__ unsigned char g_keep2[N_MAX];
__device__ double g_summary[128];
__device__ float g_v[2][64];
__device__ double g_loss[4];

__device__ int g_bsD[CSRB], g_bsS[CSRB], g_offD[CSRB], g_offS[CSRB];
__device__ int g_blkCntG[2][GB];
__device__ unsigned long long g_seedkeyG[2];
__device__ int g_hstarG[2], g_rremG[2], g_pstarG[2], g_pselBlockG[2], g_pselRemG[2];

__device__ unsigned g_barC = 0;
__device__ unsigned g_barG[2] = {0, 0};

// ============================================================================
// helpers
// ============================================================================

__device__ __forceinline__ void xsync(unsigned* ctr, unsigned nblk, unsigned& epoch) {
    __syncthreads();
    if (threadIdx.x == 0) {
        __threadfence();
        unsigned target = (epoch + 1) * nblk;
        atomicAdd(ctr, 1u);
        while (*((volatile unsigned*)ctr) < target) {}
        __threadfence();
    }
    epoch++;
    __syncthreads();
}

__device__ __forceinline__ void xexit(unsigned* ctr, unsigned nblk, unsigned epoch) {
    __syncthreads();
    if (threadIdx.x == 0) {
        __threadfence();
        unsigned target = (epoch + 1) * nblk;
        if (atomicAdd(ctr, 1u) + 1 == target) *ctr = 0;
    }
}

__device__ __forceinline__ float softplusf(float x) {
    return fmaxf(x, 0.f) + log1pf(expf(-fabsf(x)));
}

__device__ __forceinline__ unsigned long long ullmin2(unsigned long long a, unsigned long long b) {
    return a < b ? a : b;
}

__device__ __forceinline__ int blockScanInc(int v, int* sWarp) {
    int lane = threadIdx.x & 31;
    int wid = threadIdx.x >> 5;
#pragma unroll
    for (int off = 1; off < 32; off <<= 1) {
        int t = __shfl_up_sync(0xffffffffu, v, off);
        if (lane >= off) v += t;
    }
    if (lane == 31) sWarp[wid] = v;
    __syncthreads();
    if (wid == 0) {
        int w = sWarp[lane];
#pragma unroll
        for (int off = 1; off < 32; off <<= 1) {
            int t = __shfl_up_sync(0xffffffffu, w, off);
            if (lane >= off) w += t;
        }
        sWarp[lane] = w;
    }
    __syncthreads();
    return v + (wid ? sWarp[wid - 1] : 0);
}

// ============================================================================
// Kernel 1: dual CSR build + feat->fp16 + zeroing
// ============================================================================

__global__ __launch_bounds__(1024, 2)
void csr_kernel(const float* __restrict__ feat, const int* __restrict__ src,
                const int* __restrict__ dst, int e, int n) {
    unsigned epoch = 0;
    int gtid = blockIdx.x * 1024 + threadIdx.x;
    int gsz = gridDim.x * 1024;

    for (int i = gtid; i < n; i += gsz) { g_cntD[i] = 0; g_cntS[i] = 0; g_curD[i] = 0; g_curS[i] = 0; }
    if (gtid < 4) g_loss[gtid] = 0.0;
    if (gtid < 128) g_summary[gtid] = 0.0;
    if (gtid == 0) { g_rowD[n] = e; g_rowS[n] = e; }
    {
        int tot = n * 32;
        const float2* f2 = reinterpret_cast<const float2*>(feat);
        __half2* h2 = reinterpret_cast<__half2*>(g_feat16);
        for (int i = gtid; i < tot; i += gsz) h2[i] = __float22half2_rn(f2[i]);
    }
    xsync(&g_barC, gridDim.x, epoch);

    for (int i = gtid; i < e; i += gsz) {
        atomicAdd(&g_cntD[dst[i]], 1);
        atomicAdd(&g_cntS[src[i]], 1);
    }
    xsync(&g_barC, gridDim.x, epoch);

    __shared__ int sWarp[32];
    __shared__ int sRun, sTot;
    int chunk = (n + gridDim.x - 1) / gridDim.x;
    int b0 = blockIdx.x * chunk;
    int b1 = min(b0 + chunk, n);
    for (int which = 0; which < 2; which++) {
        int* cnt = which ? g_cntS : g_cntD;
        int* row = which ? g_rowS : g_rowD;
        int* bs = which ? g_bsS : g_bsD;
        if (threadIdx.x == 0) sRun = 0;
        __syncthreads();
        for (int base = b0; base < b1; base += 1024) {
            int i = base + threadIdx.x;
            int v = (i < b1) ? __ldcg(&cnt[i]) : 0;
            int incl = blockScanInc(v, sWarp);
            if (i < b1) row[i] = sRun + incl - v;
            if (threadIdx.x == 1023) sTot = incl;
            __syncthreads();
            if (threadIdx.x == 0) sRun += sTot;
            __syncthreads();
        }
        if (threadIdx.x == 0) bs[blockIdx.x] = sRun;
        __syncthreads();
    }
    xsync(&g_barC, gridDim.x, epoch);

    if (blockIdx.x == 0) {
        int b = threadIdx.x;
        int vD = (b < (int)gridDim.x) ? __ldcg(&g_bsD[b]) : 0;
        int incl = blockScanInc(vD, sWarp);
        if (b < (int)gridDim.x) g_offD[b] = incl - vD;
        int vS = (b < (int)gridDim.x) ? __ldcg(&g_bsS[b]) : 0;
        incl = blockScanInc(vS, sWarp);
        if (b < (int)gridDim.x) g_offS[b] = incl - vS;
    }
    xsync(&g_barC, gridDim.x, epoch);

    {
        int oD = __ldcg(&g_offD[blockIdx.x]);
        int oS = __ldcg(&g_offS[blockIdx.x]);
        for (int i = b0 + threadIdx.x; i < b1; i += 1024) {
            g_rowD[i] = __ldcg(&g_rowD[i]) + oD;
            g_rowS[i] = __ldcg(&g_rowS[i]) + oS;
        }
    }
    xsync(&g_barC, gridDim.x, epoch);

    for (int i = gtid; i < e; i += gsz) {
        int d = dst[i], s = src[i];
        int pd = atomicAdd(&g_curD[d], 1);
        g_colD[__ldcg(&g_rowD[d]) + pd] = s;
        int ps = atomicAdd(&g_curS[s], 1);
        g_colS[__ldcg(&g_rowS[s]) + ps] = d;
    }
    xexit(&g_barC, gridDim.x, epoch);
}

// ============================================================================
// Kernel 2: dual frontier-BFS + exact top-k selection (both perms concurrent)
// ============================================================================

__global__ __launch_bounds__(1024, 1)
void bfs_dual_kernel(const int* __restrict__ perm1, const int* __restrict__ perm2, int n, int k) {
    int g = (blockIdx.x < GB) ? 0 : 1;
    int gb = blockIdx.x - g * GB;
    const int* perm = g ? perm2 : perm1;
    unsigned char* keep = g ? g_keep2 : g_keep1;
    int* hop = g_hopG[g];
    int* invp = g_invpermG[g];
    int* hist = g_histG[g];
    unsigned* bar = &g_barG[g];
    unsigned epoch = 0;
    int gtid = gb * 1024 + threadIdx.x;
    int gsz = GB * 1024;
    const int INF = n;

    __shared__ int sWarp[32];
    __shared__ unsigned long long sK[32];

    int root = __ldg(&perm[0]);
    for (int i = gtid; i < n; i += gsz) {
        __stcg(&hop[i], (i == root) ? 0 : INF);
        __stcg(&invp[__ldg(&perm[i])], i);
    }
    for (int i = gtid; i < HIST_BINS; i += gsz) __stcg(&hist[i], 0);
    for (int i = gtid; i < MAX_SWEEPS + 8; i += gsz) __stcg(&g_szHist[g][i], 0);
    if (gtid == 0) {
        __stcg(&g_front[g][0][0], root);
        __stcg(&g_szHist[g][0], 1);
        g_seedkeyG[g] = ~0ull;
    }
    xsync(bar, GB, epoch);

    int cnt = 1;
    int t = 0;
    int lane = threadIdx.x & 31;
    while (cnt <= k && t < MAX_SWEEPS) {
        int fsz = __ldcg(&g_szHist[g][t]);
        const int* fin = g_front[g][t & 1];
        int* fout = g_front[g][(t + 1) & 1];
        int* ctr = &g_szHist[g][t + 1];
        for (int idx = gtid; idx < fsz; idx += gsz) {
            int u = __ldcg(&fin[idx]);
            int s0 = g_rowS[u], s1 = g_rowS[u + 1];
            for (int e2 = s0; e2 < s1; e2++) {
                int v = g_colS[e2];
                bool win = false;
                if (__ldcg(&hop[v]) == INF)
                    win = (atomicCAS(&hop[v], INF, t + 1) == INF);
                if (win) {
                    cg::coalesced_group grp = cg::coalesced_threads();
                    int base;
                    if (grp.thread_rank() == 0) base = atomicAdd(ctr, (int)grp.size());
                    base = grp.shfl(base, 0);
                    __stcg(&fout[base + grp.thread_rank()], v);
                }
            }
        }
        xsync(bar, GB, epoch);
        int newly = __ldcg(&g_szHist[g][t + 1]);
        t += 1;
        cnt += newly;
        if (newly == 0 && cnt <= k) {
            unsigned long long key = ~0ull;
            for (int i = gtid; i < n; i += gsz) {
                if (__ldcg(&hop[i]) == INF)
                    key = ullmin2(key, ((unsigned long long)(unsigned)__ldg(&perm[i]) << 32) | (unsigned)i);
            }
#pragma unroll
            for (int off = 16; off; off >>= 1)
                key = ullmin2(key, __shfl_down_sync(0xffffffffu, key, off));
            int wid = threadIdx.x >> 5;
            if (lane == 0) sK[wid] = key;
            __syncthreads();
            if (threadIdx.x < 32) {
                unsigned long long kk2 = sK[threadIdx.x];
#pragma unroll
                for (int off = 16; off; off >>= 1)
                    kk2 = ullmin2(kk2, __shfl_down_sync(0xffffffffu, kk2, off));
                if (threadIdx.x == 0 && kk2 != ~0ull) atomicMin(&g_seedkeyG[g], kk2);
            }
            xsync(bar, GB, epoch);
            if (gtid == 0) {
                unsigned long long kv = g_seedkeyG[g];
                int idx = (int)(unsigned)(kv & 0xffffffffull);
                __stcg(&hop[idx], t);
                __stcg(&g_front[g][t & 1][0], idx);
                __stcg(&g_szHist[g][t], 1);
                g_seedkeyG[g] = ~0ull;
            }
            cnt += 1;
            xsync(bar, GB, epoch);
        }
    }

    {
        __shared__ int sh[256];
        for (int j = threadIdx.x; j < 256; j += 1024) sh[j] = 0;
        __syncthreads();
        for (int i = gtid; i < n; i += gsz) {
            int hv = min(__ldcg(&hop[i]), 15000);
            if (hv < 256) atomicAdd(&sh[hv], 1);
            else atomicAdd(&hist[hv], 1);
        }
        __syncthreads();
        for (int j = threadIdx.x; j < 256; j += 1024)
            if (sh[j]) atomicAdd(&hist[j], sh[j]);
    }
    xsync(bar, GB, epoch);

    if (gb == 0) {
        __shared__ int sRun, sTot, sDone;
        if (threadIdx.x == 0) { sRun = 0; sDone = 0; }
        __syncthreads();
        for (int base = 0; base < HIST_BINS; base += 1024) {
            if (sDone) break;
            int h = base + threadIdx.x;
            int v = (h < HIST_BINS) ? __ldcg(&hist[h]) : 0;
            int incl = blockScanInc(v, sWarp);
            int P = sRun + incl;
            if (v > 0 && P >= k && P - v < k) { g_hstarG[g] = h; g_rremG[g] = k - (P - v); sDone = 1; }
            if (threadIdx.x == 1023) sTot = incl;
            __syncthreads();
            if (threadIdx.x == 0) sRun += sTot;
            __syncthreads();
        }
    }
    xsync(bar, GB, epoch);
    int hstar = *(volatile int*)&g_hstarG[g];
    int rrem = *(volatile int*)&g_rremG[g];

    int chunk = (n + GB - 1) / GB;
    int v0 = gb * chunk, v1 = min(v0 + chunk, n);
    {
        int c = 0;
        for (int v = v0 + threadIdx.x; v < v1; v += 1024) {
            int j = __ldcg(&invp[v]);
            c += (min(__ldcg(&hop[j]), 15000) == hstar);
        }
#pragma unroll
        for (int off = 16; off; off >>= 1) c += __shfl_down_sync(0xffffffffu, c, off);
        int wid = threadIdx.x >> 5;
        if (lane == 0) sWarp[wid] = c;
        __syncthreads();
        if (threadIdx.x < 32) {
            int r = sWarp[threadIdx.x];
#pragma unroll
            for (int off = 16; off; off >>= 1) r += __shfl_down_sync(0xffffffffu, r, off);
            if (threadIdx.x == 0) g_blkCntG[g][gb] = r;
        }
    }
    xsync(bar, GB, epoch);
    if (gb == 0) {
        int b = threadIdx.x;
        int v = (b < GB) ? __ldcg(&g_blkCntG[g][b]) : 0;
        int incl = blockScanInc(v, sWarp);
        int excl = incl - v;
        if (b < GB && v > 0 && excl < rrem && rrem <= incl) {
            g_pselBlockG[g] = b; g_pselRemG[g] = rrem - excl;
        }
    }
    xsync(bar, GB, epoch);
    if (gb == *(volatile int*)&g_pselBlockG[g]) {
        int rem = *(volatile int*)&g_pselRemG[g];
        __shared__ int sRun2, sTot2, sDone2;
        if (threadIdx.x == 0) { sRun2 = 0; sDone2 = 0; }
        __syncthreads();
        for (int base = v0; base < v1; base += 1024) {
            if (sDone2) break;
            int v = base + threadIdx.x;
            int pred = 0;
            if (v < v1) {
                int j = __ldcg(&invp[v]);
                pred = (min(__ldcg(&hop[j]), 15000) == hstar);
            }
            int incl = blockScanInc(pred, sWarp);
            int cum = sRun2 + incl;
            if (pred && cum == rem) { g_pstarG[g] = v; sDone2 = 1; }
            if (threadIdx.x == 1023) sTot2 = incl;
            __syncthreads();
            if (threadIdx.x == 0) sRun2 += sTot2;
            __syncthreads();
        }
    }
    xsync(bar, GB, epoch);
    int pstar = *(volatile int*)&g_pstarG[g];
    for (int i = gtid; i < n; i += gsz) {
        int hv = min(__ldcg(&hop[i]), 15000);
        keep[i] = (hv < hstar) || (hv == hstar && __ldg(&perm[i]) <= pstar);
    }
    xexit(bar, GB, epoch);
}

// ============================================================================
// Kernel 3: masked GCN, BOTH perms, 4 nodes per warp (tiled GEMV)
// ============================================================================

__global__ __launch_bounds__(256)
void masked_gcn_kernel(const float* __restrict__ Wenc, int n) {
    __shared__ float sW[4096];
    __shared__ float sx1[8][64][4];
    __shared__ float sx2[8][64][4];
    __shared__ double sSum[128];
    int tid = threadIdx.x;
    for (int j = tid; j < 4096; j += 256) sW[j] = Wenc[j];
    if (tid < 128) sSum[tid] = 0.0;
    __syncthreads();
    int warp = tid >> 5, lane = tid & 31;
    double A10 = 0.0, A11 = 0.0, A20 = 0.0, A21 = 0.0;

    for (int nb = (blockIdx.x * 8 + warp) * 4; nb < n; nb += gridDim.x * 32) {
        int k1d[4], k2d[4];
        int any = 0;
#pragma unroll
        for (int j = 0; j < 4; j++) {
            int node = nb + j;
            k1d[j] = (node < n) ? (int)g_keep1[node] : 0;
            k2d[j] = (node < n) ? (int)g_keep2[node] : 0;
            any |= k1d[j] | k2d[j];
        }
        if (!any) continue;

#pragma unroll
        for (int j = 0; j < 4; j++) {
            float b10 = 0.f, b11 = 0.f, b20 = 0.f, b21 = 0.f;
            int c1 = 0, c2 = 0;
            if (k1d[j] | k2d[j]) {
                int node = nb + j;
                int s0 = g_rowD[node], s1 = g_rowD[node + 1];
#pragma unroll 2
                for (int e2 = s0; e2 < s1; e2++) {
                    int s = g_colD[e2];
                    int m1 = k1d[j] & (int)g_keep1[s];
                    int m2 = k2d[j] & (int)g_keep2[s];
                    float2 f = __half22float2(*reinterpret_cast<const __half2*>(
                        g_feat16 + (size_t)s * 64 + 2 * lane));
                    if (m1) { b10 += f.x; b11 += f.y; c1++; }
                    if (m2) { b20 += f.x; b21 += f.y; c2++; }
                }
            }
            float i1 = 1.f / (float)max(c1, 1), i2 = 1.f / (float)max(c2, 1);
            sx1[warp][2 * lane][j] = b10 * i1; sx1[warp][2 * lane + 1][j] = b11 * i1;
            sx2[warp][2 * lane][j] = b20 * i2; sx2[warp][2 * lane + 1][j] = b21 * i2;
        }
        __syncwarp();

        float o1a[4] = {0, 0, 0, 0}, o1b[4] = {0, 0, 0, 0};
        float o2a[4] = {0, 0, 0, 0}, o2b[4] = {0, 0, 0, 0};
#pragma unroll 16
        for (int kk = 0; kk < 64; kk++) {
            float2 w = *reinterpret_cast<const float2*>(&sW[kk * 64 + 2 * lane]);
            float4 x1 = *reinterpret_cast<const float4*>(&sx1[warp][kk][0]);
            float4 x2 = *reinterpret_cast<const float4*>(&sx2[warp][kk][0]);
            o1a[0] += x1.x * w.x; o1b[0] += x1.x * w.y;
            o1a[1] += x1.y * w.x; o1b[1] += x1.y * w.y;
            o1a[2] += x1.z * w.x; o1b[2] += x1.z * w.y;
            o1a[3] += x1.w * w.x; o1b[3] += x1.w * w.y;
            o2a[0] += x2.x * w.x; o2b[0] += x2.x * w.y;
            o2a[1] += x2.y * w.x; o2b[1] += x2.y * w.y;
            o2a[2] += x2.z * w.x; o2b[2] += x2.z * w.y;
            o2a[3] += x2.w * w.x; o2b[3] += x2.w * w.y;
        }
#pragma unroll
        for (int j = 0; j < 4; j++) {
            if (k1d[j]) { A10 += (double)fmaxf(o1a[j], 0.f); A11 += (double)fmaxf(o1b[j], 0.f); }
            if (k2d[j]) { A20 += (double)fmaxf(o2a[j], 0.f); A21 += (double)fmaxf(o2b[j], 0.f); }
        }
        __syncwarp();
    }
    atomicAdd(&sSum[2 * lane], A10);
    atomicAdd(&sSum[2 * lane + 1], A11);
    atomicAdd(&sSum[64 + 2 * lane], A20);
    atomicAdd(&sSum[64 + 2 * lane + 1], A21);
    __syncthreads();
    if (tid < 128) {
        double v = sSum[tid];
        if (v != 0.0) atomicAdd(&g_summary[tid], v);
    }
}

// ============================================================================
// Kernel 4: v = W_disc @ sigmoid(summary/k) for both perms
// ============================================================================

__global__ void compute_v_kernel(const float* __restrict__ Wdisc, int k) {
    __shared__ float ss[2][64];
    int tid = threadIdx.x;  // 128 threads
    int p = tid >> 6, c = tid & 63;
    double s = g_summary[tid] / (double)k;
    ss[p][c] = (float)(1.0 / (1.0 + exp(-s)));
    __syncthreads();
    float v = 0.f;
#pragma unroll
    for (int b = 0; b < 64; b++) v += Wdisc[c * 64 + b] * ss[p][b];
    g_v[p][c] = v;
}

// ============================================================================
// Kernel 5: fused pos/neg GCN + BCE loss (4 nodes/warp, no h storage)
// ============================================================================

__global__ __launch_bounds__(256)
void gcnloss_kernel(const int* __restrict__ permneg, const float* __restrict__ Wenc, int n) {
    __shared__ float sW[4096];
    __shared__ float sxp[8][64][4];
    __shared__ float sxn[8][64][4];
    __shared__ float sv[128];
    __shared__ double sL[4];
    int tid = threadIdx.x;
    for (int j = tid; j < 4096; j += 256) sW[j] = Wenc[j];
    if (tid < 64) { sv[tid] = g_v[0][tid]; sv[64 + tid] = g_v[1][tid]; }
    if (tid < 4) sL[tid] = 0.0;
    __syncthreads();
    int warp = tid >> 5, lane = tid & 31;
    float v0a = sv[2 * lane], v0b = sv[2 * lane + 1];
    float v1a = sv[64 + 2 * lane], v1b = sv[64 + 2 * lane + 1];
    double l0 = 0, l1 = 0, l2 = 0, l3 = 0;

    for (int nb = (blockIdx.x * 8 + warp) * 4; nb < n; nb += gridDim.x * 32) {
#pragma unroll
        for (int j = 0; j < 4; j++) {
            int node = nb + j;
            float ap0 = 0.f, ap1 = 0.f, an0 = 0.f, an1 = 0.f;
            int deg = 1;
            if (node < n) {
                int s0 = g_rowD[node], s1 = g_rowD[node + 1];
                deg = max(s1 - s0, 1);
#pragma unroll 2
                for (int e2 = s0; e2 < s1; e2++) {
                    int s = g_colD[e2];
                    int r = __ldg(&permneg[s]);
                    float2 fp = __half22float2(*reinterpret_cast<const __half2*>(
                        g_feat16 + (size_t)s * 64 + 2 * lane));
                    float2 fn = __half22float2(*reinterpret_cast<const __half2*>(
                        g_feat16 + (size_t)r * 64 + 2 * lane));
                    ap0 += fp.x; ap1 += fp.y; an0 += fn.x; an1 += fn.y;
                }
            }
            float invd = 1.f / (float)deg;
            sxp[warp][2 * lane][j] = ap0 * invd; sxp[warp][2 * lane + 1][j] = ap1 * invd;
            sxn[warp][2 * lane][j] = an0 * invd; sxn[warp][2 * lane + 1][j] = an1 * invd;
        }
        __syncwarp();

        float opa[4] = {0, 0, 0, 0}, opb[4] = {0, 0, 0, 0};
        float ona[4] = {0, 0, 0, 0}, onb[4] = {0, 0, 0, 0};
#pragma unroll 16
        for (int kk = 0; kk < 64; kk++) {
            float2 w = *reinterpret_cast<const float2*>(&sW[kk * 64 + 2 * lane]);
            float4 xp = *reinterpret_cast<const float4*>(&sxp[warp][kk][0]);
            float4 xn = *reinterpret_cast<const float4*>(&sxn[warp][kk][0]);
            opa[0] += xp.x * w.x; opb[0] += xp.x * w.y;
            opa[1] += xp.y * w.x; opb[1] += xp.y * w.y;
            opa[2] += xp.z * w.x; opb[2] += xp.z * w.y;
            opa[3] += xp.w * w.x; opb[3] += xp.w * w.y;
            ona[0] += xn.x * w.x; onb[0] += xn.x * w.y;
            ona[1] += xn.y * w.x; onb[1] += xn.y * w.y;
            ona[2] += xn.z * w.x; onb[2] += xn.z * w.y;
            ona[3] += xn.w * w.x; onb[3] += xn.w * w.y;
        }
#pragma unroll
        for (int j = 0; j < 4; j++) {
            float hp0 = fmaxf(opa[j], 0.f), hp1 = fmaxf(opb[j], 0.f);
            float hn0 = fmaxf(ona[j], 0.f), hn1 = fmaxf(onb[j], 0.f);
            float p1 = hp0 * v0a + hp1 * v0b;
            float p2 = hp0 * v1a + hp1 * v1b;
            float q1 = hn0 * v0a + hn1 * v0b;
            float q2 = hn0 * v1a + hn1 * v1b;
#pragma unroll
            for (int off = 16; off; off >>= 1) {
                p1 += __shfl_down_sync(0xffffffffu, p1, off);
                p2 += __shfl_down_sync(0xffffffffu, p2, off);
                q1 += __shfl_down_sync(0xffffffffu, q1, off);
                q2 += __shfl_down_sync(0xffffffffu, q2, off);
            }
            if (lane == 0 && nb + j < n) {
                l0 += (double)softplusf(-p1);
                l1 += (double)softplusf(q1);
                l2 += (double)softplusf(-p2);
                l3 += (double)softplusf(q2);
            }
        }
        __syncwarp();
    }
    if (lane == 0) {
        atomicAdd(&sL[0], l0); atomicAdd(&sL[1], l1);
        atomicAdd(&sL[2], l2); atomicAdd(&sL[3], l3);
    }
    __syncthreads();
    if (tid < 4) atomicAdd(&g_loss[tid], sL[tid]);
}

__global__ void finalize_kernel(float* out, int n) {
    out[0] = (float)((g_loss[0] + g_loss[1] + g_loss[2] + g_loss[3]) / (double)n);
}

// ============================================================================
// launch
// ============================================================================

extern "C" void kernel_launch(void* const* d_in, const int* in_sizes, int n_in,
                              void* d_out, int out_size) {
    const float* feat = (const float*)d_in[0];
    const float* Wenc = (const float*)d_in[1];
    const float* Wdisc = (const float*)d_in[2];
    const int* src = (const int*)d_in[3];
    const int* dst = (const int*)d_in[4];
    const int* permneg = (const int*)d_in[5];
    const int* perm1 = (const int*)d_in[6];
    const int* perm2 = (const int*)d_in[7];

    int e = in_sizes[3];
    int n = in_sizes[5];
    int k = (int)((double)n * 0.8);

    csr_kernel<<<CSRB, 1024>>>(feat, src, dst, e, n);
    bfs_dual_kernel<<<BFSB, 1024>>>(perm1, perm2, n, k);

    int dGrid = (n + 31) / 32;   // 4 nodes/warp * 8 warps/block
    masked_gcn_kernel<<<dGrid, 256>>>(Wenc, n);
    compute_v_kernel<<<1, 128>>>(Wdisc, k);
    gcnloss_kernel<<<dGrid, 256>>>(permneg, Wenc, n);
    finalize_kernel<<<1, 1>>>((float*)d_out, n);
}

// round 7
// speedup vs baseline: 1.1460x; 1.0869x over previous
#include <cuda_runtime.h>
#include <cuda_fp16.h>
#include <cooperative_groups.h>
#include <math.h>

namespace cg = cooperative_groups;

// ============================================================================
// DGISubgraphCL — 4-launch pipeline:
//   csr (dual CSR + fp16 feat) -> dual frontier-BFS + top-k ->
//   mega GCN (pos+neg+mask1+mask2 in one gather pass; last block computes v)
//   -> loss (streams h; last block finalizes output).
// ============================================================================

#define N_MAX 131072
#define E_MAX (N_MAX * 17)
#define HIST_BINS 15001
#define CSRB 264
#define BFSB 132
#define GB 66
#define MAX_SWEEPS 250

// ---- device scratch ----
__device__ int g_rowD[N_MAX + 1], g_cntD[N_MAX], g_curD[N_MAX];
__device__ int g_rowS[N_MAX + 1], g_cntS[N_MAX], g_curS[N_MAX];
__device__ int g_colD[E_MAX];
__device__ int g_colS[E_MAX];
__device__ __half g_feat16[(size_t)N_MAX * 64];
__device__ int g_hopG[2][N_MAX];
__device__ int g_front[2][2][N_MAX];
__device__ int g_invpermG[2][N_MAX];
__device__ int g_histG[2][HIST_BINS];
__device__ int g_szHist[2][MAX_SWEEPS + 8];
__device__ unsigned char g_keep1[N_MAX];
__device__ unsigned char g_keep2[N_MAX];
__device__ float g_hpos[(size_t)N_MAX * 64];
__device__ float g_hneg[(size_t)N_MAX * 64];
__device__ double g_summary[128];
__device__ float g_v[2][64];
__device__ double g_loss[4];

__device__ int g_bsD[CSRB], g_bsS[CSRB], g_offD[CSRB], g_offS[CSRB];
__device__ int g_blkCntG[2][GB];
__device__ unsigned long long g_seedkeyG[2];
__device__ int g_hstarG[2], g_rremG[2], g_pstarG[2], g_pselBlockG[2], g_pselRemG[2];

__device__ unsigned g_barC = 0;
__device__ unsigned g_barG[2] = {0, 0};
__device__ unsigned g_ctrMega = 0;
__device__ unsigned g_ctrLoss = 0;

// ============================================================================
// helpers
// ============================================================================

__device__ __forceinline__ void xsync(unsigned* ctr, unsigned nblk, unsigned& epoch) {
    __syncthreads();
    if (threadIdx.x == 0) {
        __threadfence();
        unsigned target = (epoch + 1) * nblk;
        atomicAdd(ctr, 1u);
        while (*((volatile unsigned*)ctr) < target) {}
        __threadfence();
    }
    epoch++;
    __syncthreads();
}

__device__ __forceinline__ void xexit(unsigned* ctr, unsigned nblk, unsigned epoch) {
    __syncthreads();
    if (threadIdx.x == 0) {
        __threadfence();
        unsigned target = (epoch + 1) * nblk;
        if (atomicAdd(ctr, 1u) + 1 == target) *ctr = 0;
    }
}

__device__ __forceinline__ float softplusf(float x) {
    return fmaxf(x, 0.f) + log1pf(expf(-fabsf(x)));
}

__device__ __forceinline__ unsigned long long ullmin2(unsigned long long a, unsigned long long b) {
    return a < b ? a : b;
}

__device__ __forceinline__ int blockScanInc(int v, int* sWarp) {
    int lane = threadIdx.x & 31;
    int wid = threadIdx.x >> 5;
#pragma unroll
    for (int off = 1; off < 32; off <<= 1) {
        int t = __shfl_up_sync(0xffffffffu, v, off);
        if (lane >= off) v += t;
    }
    if (lane == 31) sWarp[wid] = v;
    __syncthreads();
    if (wid == 0) {
        int w = sWarp[lane];
#pragma unroll
        for (int off = 1; off < 32; off <<= 1) {
            int t = __shfl_up_sync(0xffffffffu, w, off);
            if (lane >= off) w += t;
        }
        sWarp[lane] = w;
    }
    __syncthreads();
    return v + (wid ? sWarp[wid - 1] : 0);
}

// ============================================================================
// Kernel 1: dual CSR build + feat->fp16 + zeroing
// ============================================================================

__global__ __launch_bounds__(1024, 2)
void csr_kernel(const float* __restrict__ feat, const int* __restrict__ src,
                const int* __restrict__ dst, int e, int n) {
    unsigned epoch = 0;
    int gtid = blockIdx.x * 1024 + threadIdx.x;
    int gsz = gridDim.x * 1024;

    for (int i = gtid; i < n; i += gsz) { g_cntD[i] = 0; g_cntS[i] = 0; g_curD[i] = 0; g_curS[i] = 0; }
    if (gtid < 4) g_loss[gtid] = 0.0;
    if (gtid < 128) g_summary[gtid] = 0.0;
    if (gtid == 0) { g_rowD[n] = e; g_rowS[n] = e; }
    {
        int tot = n * 32;
        const float2* f2 = reinterpret_cast<const float2*>(feat);
        __half2* h2 = reinterpret_cast<__half2*>(g_feat16);
        for (int i = gtid; i < tot; i += gsz) h2[i] = __float22half2_rn(f2[i]);
    }
    xsync(&g_barC, gridDim.x, epoch);

    for (int i = gtid; i < e; i += gsz) {
        atomicAdd(&g_cntD[dst[i]], 1);
        atomicAdd(&g_cntS[src[i]], 1);
    }
    xsync(&g_barC, gridDim.x, epoch);

    __shared__ int sWarp[32];
    __shared__ int sRun, sTot;
    int chunk = (n + gridDim.x - 1) / gridDim.x;
    int b0 = blockIdx.x * chunk;
    int b1 = min(b0 + chunk, n);
    for (int which = 0; which < 2; which++) {
        int* cnt = which ? g_cntS : g_cntD;
        int* row = which ? g_rowS : g_rowD;
        int* bs = which ? g_bsS : g_bsD;
        if (threadIdx.x == 0) sRun = 0;
        __syncthreads();
        for (int base = b0; base < b1; base += 1024) {
            int i = base + threadIdx.x;
            int v = (i < b1) ? __ldcg(&cnt[i]) : 0;
            int incl = blockScanInc(v, sWarp);
            if (i < b1) row[i] = sRun + incl - v;
            if (threadIdx.x == 1023) sTot = incl;
            __syncthreads();
            if (threadIdx.x == 0) sRun += sTot;
            __syncthreads();
        }
        if (threadIdx.x == 0) bs[blockIdx.x] = sRun;
        __syncthreads();
    }
    xsync(&g_barC, gridDim.x, epoch);

    if (blockIdx.x == 0) {
        int b = threadIdx.x;
        int vD = (b < (int)gridDim.x) ? __ldcg(&g_bsD[b]) : 0;
        int incl = blockScanInc(vD, sWarp);
        if (b < (int)gridDim.x) g_offD[b] = incl - vD;
        int vS = (b < (int)gridDim.x) ? __ldcg(&g_bsS[b]) : 0;
        incl = blockScanInc(vS, sWarp);
        if (b < (int)gridDim.x) g_offS[b] = incl - vS;
    }
    xsync(&g_barC, gridDim.x, epoch);

    {
        int oD = __ldcg(&g_offD[blockIdx.x]);
        int oS = __ldcg(&g_offS[blockIdx.x]);
        for (int i = b0 + threadIdx.x; i < b1; i += 1024) {
            g_rowD[i] = __ldcg(&g_rowD[i]) + oD;
            g_rowS[i] = __ldcg(&g_rowS[i]) + oS;
        }
    }
    xsync(&g_barC, gridDim.x, epoch);

    for (int i = gtid; i < e; i += gsz) {
        int d = dst[i], s = src[i];
        int pd = atomicAdd(&g_curD[d], 1);
        g_colD[__ldcg(&g_rowD[d]) + pd] = s;
        int ps = atomicAdd(&g_curS[s], 1);
        g_colS[__ldcg(&g_rowS[s]) + ps] = d;
    }
    xexit(&g_barC, gridDim.x, epoch);
}

// ============================================================================
// Kernel 2: dual frontier-BFS + exact top-k selection (both perms concurrent)
// ============================================================================

__global__ __launch_bounds__(1024, 1)
void bfs_dual_kernel(const int* __restrict__ perm1, const int* __restrict__ perm2, int n, int k) {
    int g = (blockIdx.x < GB) ? 0 : 1;
    int gb = blockIdx.x - g * GB;
    const int* perm = g ? perm2 : perm1;
    unsigned char* keep = g ? g_keep2 : g_keep1;
    int* hop = g_hopG[g];
    int* invp = g_invpermG[g];
    int* hist = g_histG[g];
    unsigned* bar = &g_barG[g];
    unsigned epoch = 0;
    int gtid = gb * 1024 + threadIdx.x;
    int gsz = GB * 1024;
    const int INF = n;

    __shared__ int sWarp[32];
    __shared__ unsigned long long sK[32];

    int root = __ldg(&perm[0]);
    for (int i = gtid; i < n; i += gsz) {
        __stcg(&hop[i], (i == root) ? 0 : INF);
        __stcg(&invp[__ldg(&perm[i])], i);
    }
    for (int i = gtid; i < HIST_BINS; i += gsz) __stcg(&hist[i], 0);
    for (int i = gtid; i < MAX_SWEEPS + 8; i += gsz) __stcg(&g_szHist[g][i], 0);
    if (gtid == 0) {
        __stcg(&g_front[g][0][0], root);
        __stcg(&g_szHist[g][0], 1);
        g_seedkeyG[g] = ~0ull;
    }
    xsync(bar, GB, epoch);

    int cnt = 1;
    int t = 0;
    int lane = threadIdx.x & 31;
    while (cnt <= k && t < MAX_SWEEPS) {
        int fsz = __ldcg(&g_szHist[g][t]);
        const int* fin = g_front[g][t & 1];
        int* fout = g_front[g][(t + 1) & 1];
        int* ctr = &g_szHist[g][t + 1];
        for (int idx = gtid; idx < fsz; idx += gsz) {
            int u = __ldcg(&fin[idx]);
            int s0 = g_rowS[u], s1 = g_rowS[u + 1];
            for (int e2 = s0; e2 < s1; e2++) {
                int v = g_colS[e2];
                bool win = false;
                if (__ldcg(&hop[v]) == INF)
                    win = (atomicCAS(&hop[v], INF, t + 1) == INF);
                if (win) {
                    cg::coalesced_group grp = cg::coalesced_threads();
                    int base;
                    if (grp.thread_rank() == 0) base = atomicAdd(ctr, (int)grp.size());
                    base = grp.shfl(base, 0);
                    __stcg(&fout[base + grp.thread_rank()], v);
                }
            }
        }
        xsync(bar, GB, epoch);
        int newly = __ldcg(&g_szHist[g][t + 1]);
        t += 1;
        cnt += newly;
        if (newly == 0 && cnt <= k) {
            unsigned long long key = ~0ull;
            for (int i = gtid; i < n; i += gsz) {
                if (__ldcg(&hop[i]) == INF)
                    key = ullmin2(key, ((unsigned long long)(unsigned)__ldg(&perm[i]) << 32) | (unsigned)i);
            }
#pragma unroll
            for (int off = 16; off; off >>= 1)
                key = ullmin2(key, __shfl_down_sync(0xffffffffu, key, off));
            int wid = threadIdx.x >> 5;
            if (lane == 0) sK[wid] = key;
            __syncthreads();
            if (threadIdx.x < 32) {
                unsigned long long kk2 = sK[threadIdx.x];
#pragma unroll
                for (int off = 16; off; off >>= 1)
                    kk2 = ullmin2(kk2, __shfl_down_sync(0xffffffffu, kk2, off));
                if (threadIdx.x == 0 && kk2 != ~0ull) atomicMin(&g_seedkeyG[g], kk2);
            }
            xsync(bar, GB, epoch);
            if (gtid == 0) {
                unsigned long long kv = g_seedkeyG[g];
                int idx = (int)(unsigned)(kv & 0xffffffffull);
                __stcg(&hop[idx], t);
                __stcg(&g_front[g][t & 1][0], idx);
                __stcg(&g_szHist[g][t], 1);
                g_seedkeyG[g] = ~0ull;
            }
            cnt += 1;
            xsync(bar, GB, epoch);
        }
    }

    {
        __shared__ int sh[256];
        for (int j = threadIdx.x; j < 256; j += 1024) sh[j] = 0;
        __syncthreads();
        for (int i = gtid; i < n; i += gsz) {
            int hv = min(__ldcg(&hop[i]), 15000);
            if (hv < 256) atomicAdd(&sh[hv], 1);
            else atomicAdd(&hist[hv], 1);
        }
        __syncthreads();
        for (int j = threadIdx.x; j < 256; j += 1024)
            if (sh[j]) atomicAdd(&hist[j], sh[j]);
    }
    xsync(bar, GB, epoch);

    if (gb == 0) {
        __shared__ int sRun, sTot, sDone;
        if (threadIdx.x == 0) { sRun = 0; sDone = 0; }
        __syncthreads();
        for (int base = 0; base < HIST_BINS; base += 1024) {
            if (sDone) break;
            int h = base + threadIdx.x;
            int v = (h < HIST_BINS) ? __ldcg(&hist[h]) : 0;
            int incl = blockScanInc(v, sWarp);
            int P = sRun + incl;
            if (v > 0 && P >= k && P - v < k) { g_hstarG[g] = h; g_rremG[g] = k - (P - v); sDone = 1; }
            if (threadIdx.x == 1023) sTot = incl;
            __syncthreads();
            if (threadIdx.x == 0) sRun += sTot;
            __syncthreads();
        }
    }
    xsync(bar, GB, epoch);
    int hstar = *(volatile int*)&g_hstarG[g];
    int rrem = *(volatile int*)&g_rremG[g];

    int chunk = (n + GB - 1) / GB;
    int v0 = gb * chunk, v1 = min(v0 + chunk, n);
    {
        int c = 0;
        for (int v = v0 + threadIdx.x; v < v1; v += 1024) {
            int j = __ldcg(&invp[v]);
            c += (min(__ldcg(&hop[j]), 15000) == hstar);
        }
#pragma unroll
        for (int off = 16; off; off >>= 1) c += __shfl_down_sync(0xffffffffu, c, off);
        int wid = threadIdx.x >> 5;
        if (lane == 0) sWarp[wid] = c;
        __syncthreads();
        if (threadIdx.x < 32) {
            int r = sWarp[threadIdx.x];
#pragma unroll
            for (int off = 16; off; off >>= 1) r += __shfl_down_sync(0xffffffffu, r, off);
            if (threadIdx.x == 0) g_blkCntG[g][gb] = r;
        }
    }
    xsync(bar, GB, epoch);
    if (gb == 0) {
        int b = threadIdx.x;
        int v = (b < GB) ? __ldcg(&g_blkCntG[g][b]) : 0;
        int incl = blockScanInc(v, sWarp);
        int excl = incl - v;
        if (b < GB && v > 0 && excl < rrem && rrem <= incl) {
            g_pselBlockG[g] = b; g_pselRemG[g] = rrem - excl;
        }
    }
    xsync(bar, GB, epoch);
    if (gb == *(volatile int*)&g_pselBlockG[g]) {
        int rem = *(volatile int*)&g_pselRemG[g];
        __shared__ int sRun2, sTot2, sDone2;
        if (threadIdx.x == 0) { sRun2 = 0; sDone2 = 0; }
        __syncthreads();
        for (int base = v0; base < v1; base += 1024) {
            if (sDone2) break;
            int v = base + threadIdx.x;
            int pred = 0;
            if (v < v1) {
                int j = __ldcg(&invp[v]);
                pred = (min(__ldcg(&hop[j]), 15000) == hstar);
            }
            int incl = blockScanInc(pred, sWarp);
            int cum = sRun2 + incl;
            if (pred && cum == rem) { g_pstarG[g] = v; sDone2 = 1; }
            if (threadIdx.x == 1023) sTot2 = incl;
            __syncthreads();
            if (threadIdx.x == 0) sRun2 += sTot2;
            __syncthreads();
        }
    }
    xsync(bar, GB, epoch);
    int pstar = *(volatile int*)&g_pstarG[g];
    for (int i = gtid; i < n; i += gsz) {
        int hv = min(__ldcg(&hop[i]), 15000);
        keep[i] = (hv < hstar) || (hv == hstar && __ldg(&perm[i]) <= pstar);
    }
    xexit(bar, GB, epoch);
}

// ============================================================================
// Kernel 3: mega GCN — pos+neg+mask1+mask2 in ONE gather pass (2 rows/edge),
// predicated mask accumulation, 2 nodes/warp tiled GEMV, writes hpos/hneg,
// accumulates summaries; LAST block computes v = Wdisc @ sigmoid(summary/k).
// ============================================================================

__global__ __launch_bounds__(256)
void mega_gcn_kernel(const int* __restrict__ permneg, const float* __restrict__ Wenc,
                     const float* __restrict__ Wdisc, int n, int k) {
    __shared__ float sW[4096];
    __shared__ float sxp[8][64][2];
    __shared__ float sxn[8][64][2];
    __shared__ float sx1[8][64][2];
    __shared__ float sx2[8][64][2];
    __shared__ double sSum[128];
    __shared__ int sLast;
    int tid = threadIdx.x;
    for (int j = tid; j < 4096; j += 256) sW[j] = Wenc[j];
    if (tid < 128) sSum[tid] = 0.0;
    __syncthreads();
    int warp = tid >> 5, lane = tid & 31;
    double A10 = 0.0, A11 = 0.0, A20 = 0.0, A21 = 0.0;

    for (int nb = (blockIdx.x * 8 + warp) * 2; nb < n; nb += gridDim.x * 16) {
        int k1d[2], k2d[2];
#pragma unroll
        for (int j = 0; j < 2; j++) {
            int node = nb + j;
            bool valid = node < n;
            k1d[j] = valid ? (int)g_keep1[node] : 0;
            k2d[j] = valid ? (int)g_keep2[node] : 0;
            int s0 = valid ? g_rowD[node] : 0;
            int s1 = valid ? g_rowD[node + 1] : 0;

            float p0 = 0.f, p1 = 0.f, q0 = 0.f, q1 = 0.f;
            float m10 = 0.f, m11 = 0.f, m20 = 0.f, m21 = 0.f;
            int c1 = 0, c2 = 0;

            int e2 = s0;
            for (; e2 + 2 <= s1; e2 += 2) {
                int sA = g_colD[e2], sB = g_colD[e2 + 1];
                int rA = __ldg(&permneg[sA]), rB = __ldg(&permneg[sB]);
                __half2 hA = *reinterpret_cast<const __half2*>(g_feat16 + (size_t)sA * 64 + 2 * lane);
                __half2 hB = *reinterpret_cast<const __half2*>(g_feat16 + (size_t)sB * 64 + 2 * lane);
                __half2 hnA = *reinterpret_cast<const __half2*>(g_feat16 + (size_t)rA * 64 + 2 * lane);
                __half2 hnB = *reinterpret_cast<const __half2*>(g_feat16 + (size_t)rB * 64 + 2 * lane);
                int kA1 = k1d[j] & (int)g_keep1[sA], kB1 = k1d[j] & (int)g_keep1[sB];
                int kA2 = k2d[j] & (int)g_keep2[sA], kB2 = k2d[j] & (int)g_keep2[sB];
                float2 fA = __half22float2(hA), fB = __half22float2(hB);
                float2 fnA = __half22float2(hnA), fnB = __half22float2(hnB);
                p0 += fA.x + fB.x; p1 += fA.y + fB.y;
                q0 += fnA.x + fnB.x; q1 += fnA.y + fnB.y;
                float wA1 = (float)kA1, wB1 = (float)kB1;
                float wA2 = (float)kA2, wB2 = (float)kB2;
                m10 += fA.x * wA1 + fB.x * wB1; m11 += fA.y * wA1 + fB.y * wB1;
                m20 += fA.x * wA2 + fB.x * wB2; m21 += fA.y * wA2 + fB.y * wB2;
                c1 += kA1 + kB1; c2 += kA2 + kB2;
            }
            if (e2 < s1) {
                int sA = g_colD[e2];
                int rA = __ldg(&permneg[sA]);
                float2 fA = __half22float2(*reinterpret_cast<const __half2*>(
                    g_feat16 + (size_t)sA * 64 + 2 * lane));
                float2 fnA = __half22float2(*reinterpret_cast<const __half2*>(
                    g_feat16 + (size_t)rA * 64 + 2 * lane));
                int kA1 = k1d[j] & (int)g_keep1[sA];
                int kA2 = k2d[j] & (int)g_keep2[sA];
                p0 += fA.x; p1 += fA.y; q0 += fnA.x; q1 += fnA.y;
                float wA1 = (float)kA1, wA2 = (float)kA2;
                m10 += fA.x * wA1; m11 += fA.y * wA1;
                m20 += fA.x * wA2; m21 += fA.y * wA2;
                c1 += kA1; c2 += kA2;
            }

            float invd = 1.f / (float)max(s1 - s0, 1);
            float i1 = 1.f / (float)max(c1, 1);
            float i2 = 1.f / (float)max(c2, 1);
            sxp[warp][2 * lane][j] = p0 * invd; sxp[warp][2 * lane + 1][j] = p1 * invd;
            sxn[warp][2 * lane][j] = q0 * invd; sxn[warp][2 * lane + 1][j] = q1 * invd;
            sx1[warp][2 * lane][j] = m10 * i1;  sx1[warp][2 * lane + 1][j] = m11 * i1;
            sx2[warp][2 * lane][j] = m20 * i2;  sx2[warp][2 * lane + 1][j] = m21 * i2;
        }
        __syncwarp();

        float opa[2] = {0, 0}, opb[2] = {0, 0};
        float ona[2] = {0, 0}, onb[2] = {0, 0};
        float o1a[2] = {0, 0}, o1b[2] = {0, 0};
        float o2a[2] = {0, 0}, o2b[2] = {0, 0};
#pragma unroll 16
        for (int kk = 0; kk < 64; kk++) {
            float2 w = *reinterpret_cast<const float2*>(&sW[kk * 64 + 2 * lane]);
            float2 xp = *reinterpret_cast<const float2*>(&sxp[warp][kk][0]);
            float2 xn = *reinterpret_cast<const float2*>(&sxn[warp][kk][0]);
            float2 x1 = *reinterpret_cast<const float2*>(&sx1[warp][kk][0]);
            float2 x2 = *reinterpret_cast<const float2*>(&sx2[warp][kk][0]);
            opa[0] += xp.x * w.x; opb[0] += xp.x * w.y;
            opa[1] += xp.y * w.x; opb[1] += xp.y * w.y;
            ona[0] += xn.x * w.x; onb[0] += xn.x * w.y;
            ona[1] += xn.y * w.x; onb[1] += xn.y * w.y;
            o1a[0] += x1.x * w.x; o1b[0] += x1.x * w.y;
            o1a[1] += x1.y * w.x; o1b[1] += x1.y * w.y;
            o2a[0] += x2.x * w.x; o2b[0] += x2.x * w.y;
            o2a[1] += x2.y * w.x; o2b[1] += x2.y * w.y;
        }
#pragma unroll
        for (int j = 0; j < 2; j++) {
            int node = nb + j;
            if (node < n) {
                *reinterpret_cast<float2*>(g_hpos + (size_t)node * 64 + 2 * lane) =
                    make_float2(fmaxf(opa[j], 0.f), fmaxf(opb[j], 0.f));
                *reinterpret_cast<float2*>(g_hneg + (size_t)node * 64 + 2 * lane) =
                    make_float2(fmaxf(ona[j], 0.f), fmaxf(onb[j], 0.f));
                if (k1d[j]) { A10 += (double)fmaxf(o1a[j], 0.f); A11 += (double)fmaxf(o1b[j], 0.f); }
                if (k2d[j]) { A20 += (double)fmaxf(o2a[j], 0.f); A21 += (double)fmaxf(o2b[j], 0.f); }
            }
        }
        __syncwarp();
    }
    atomicAdd(&sSum[2 * lane], A10);
    atomicAdd(&sSum[2 * lane + 1], A11);
    atomicAdd(&sSum[64 + 2 * lane], A20);
    atomicAdd(&sSum[64 + 2 * lane + 1], A21);
    __syncthreads();
    if (tid < 128) {
        double v = sSum[tid];
        if (v != 0.0) atomicAdd(&g_summary[tid], v);
    }

    // last block computes v
    if (tid == 0) {
        __threadfence();
        sLast = (atomicAdd(&g_ctrMega, 1u) == gridDim.x - 1);
    }
    __syncthreads();
    if (sLast) {
        __shared__ float ss[2][64];
        if (tid < 128) {
            double s = g_summary[tid] / (double)k;
            ss[tid >> 6][tid & 63] = (float)(1.0 / (1.0 + exp(-s)));
        }
        __syncthreads();
        if (tid < 128) {
            int p = tid >> 6, c = tid & 63;
            float v = 0.f;
#pragma unroll
            for (int b = 0; b < 64; b++) v += Wdisc[c * 64 + b] * ss[p][b];
            g_v[p][c] = v;
        }
        if (tid == 0) g_ctrMega = 0;
    }
}

// ============================================================================
// Kernel 4: BCE losses (streams hpos/hneg); last block writes final output.
// ============================================================================

__global__ __launch_bounds__(256)
void loss_kernel(float* __restrict__ out, int n) {
    __shared__ float sv0[64], sv1[64];
    __shared__ double sL[4];
    __shared__ int sLast;
    int tid = threadIdx.x;
    if (tid < 64) { sv0[tid] = g_v[0][tid]; sv1[tid] = g_v[1][tid]; }
    if (tid < 4) sL[tid] = 0.0;
    __syncthreads();
    int warp = tid >> 5, lane = tid & 31;
    float v00 = sv0[2 * lane], v01 = sv0[2 * lane + 1];
    float v10 = sv1[2 * lane], v11 = sv1[2 * lane + 1];
    double l0 = 0, l1 = 0, l2 = 0, l3 = 0;
    for (int node = blockIdx.x * 8 + warp; node < n; node += gridDim.x * 8) {
        float2 hp = *reinterpret_cast<const float2*>(g_hpos + (size_t)node * 64 + 2 * lane);
        float2 hn = *reinterpret_cast<const float2*>(g_hneg + (size_t)node * 64 + 2 * lane);
        float p1 = hp.x * v00 + hp.y * v01;
        float p2 = hp.x * v10 + hp.y * v11;
        float q1 = hn.x * v00 + hn.y * v01;
        float q2 = hn.x * v10 + hn.y * v11;
#pragma unroll
        for (int off = 16; off; off >>= 1) {
            p1 += __shfl_down_sync(0xffffffffu, p1, off);
            p2 += __shfl_down_sync(0xffffffffu, p2, off);
            q1 += __shfl_down_sync(0xffffffffu, q1, off);
            q2 += __shfl_down_sync(0xffffffffu, q2, off);
        }
        if (lane == 0) {
            l0 += (double)softplusf(-p1);
            l1 += (double)softplusf(q1);
            l2 += (double)softplusf(-p2);
            l3 += (double)softplusf(q2);
        }
    }
    if (lane == 0) {
        atomicAdd(&sL[0], l0); atomicAdd(&sL[1], l1);
        atomicAdd(&sL[2], l2); atomicAdd(&sL[3], l3);
    }
    __syncthreads();
    if (tid < 4) atomicAdd(&g_loss[tid], sL[tid]);

    if (tid == 0) {
        __threadfence();
        sLast = (atomicAdd(&g_ctrLoss, 1u) == gridDim.x - 1);
    }
    __syncthreads();
    if (sLast && tid == 0) {
        out[0] = (float)((g_loss[0] + g_loss[1] + g_loss[2] + g_loss[3]) / (double)n);
        g_ctrLoss = 0;
    }
}

// ============================================================================
// launch
// ============================================================================

extern "C" void kernel_launch(void* const* d_in, const int* in_sizes, int n_in,
                              void* d_out, int out_size) {
    const float* feat = (const float*)d_in[0];
    const float* Wenc = (const float*)d_in[1];
    const float* Wdisc = (const float*)d_in[2];
    const int* src = (const int*)d_in[3];
    const int* dst = (const int*)d_in[4];
    const int* permneg = (const int*)d_in[5];
    const int* perm1 = (const int*)d_in[6];
    const int* perm2 = (const int*)d_in[7];

    int e = in_sizes[3];
    int n = in_sizes[5];
    int k = (int)((double)n * 0.8);

    csr_kernel<<<CSRB, 1024>>>(feat, src, dst, e, n);
    bfs_dual_kernel<<<BFSB, 1024>>>(perm1, perm2, n, k);

    int mGrid = (n + 15) / 16;            // 2 nodes/warp * 8 warps/block
    if (mGrid > 1480) mGrid = 1480;       // stride loop; bounds summary atomics
    mega_gcn_kernel<<<mGrid, 256>>>(permneg, Wenc, Wdisc, n, k);

    int lGrid = (n + 7) / 8;
    if (lGrid > 1480) lGrid = 1480;
    loss_kernel<<<lGrid, 256>>>((float*)d_out, n);
}

// round 8
// speedup vs baseline: 1.2206x; 1.0650x over previous
#include <cuda_runtime.h>
#include <cuda_fp16.h>
#include <cooperative_groups.h>
#include <math.h>

namespace cg = cooperative_groups;

// ============================================================================
// DGISubgraphCL — 5-launch pipeline:
//   csr (dual CSR + fp16 feat + permuted neg feat) -> dual frontier-BFS +
//   top-k -> annotate (pack keep bits into colD) -> mega GCN (4 aggregations,
//   one annotated gather pass; last block computes v) -> loss (fp16 h).
// ============================================================================

#define N_MAX 131072
#define E_MAX (N_MAX * 17)
#define HIST_BINS 15001
#define CSRB 264
#define BFSB 132
#define GB 66
#define MAX_SWEEPS 250

// ---- device scratch ----
__device__ int g_rowD[N_MAX + 1], g_cntD[N_MAX], g_curD[N_MAX];
__device__ int g_rowS[N_MAX + 1], g_cntS[N_MAX], g_curS[N_MAX];
__device__ unsigned g_colD[E_MAX];          // after annotate: s | k1<<30 | k2<<31
__device__ int g_colS[E_MAX];
__device__ __half g_feat16[(size_t)N_MAX * 64];
__device__ __half g_featneg16[(size_t)N_MAX * 64];
__device__ int g_hopG[2][N_MAX];
__device__ int g_front[2][2][N_MAX];
__device__ int g_invpermG[2][N_MAX];
__device__ int g_histG[2][HIST_BINS];
__device__ int g_szHist[2][MAX_SWEEPS + 8];
__device__ unsigned char g_keep1[N_MAX];
__device__ unsigned char g_keep2[N_MAX];
__device__ __half g_hpos16[(size_t)N_MAX * 64];
__device__ __half g_hneg16[(size_t)N_MAX * 64];
__device__ double g_summary[128];
__device__ float g_v[2][64];
__device__ double g_loss[4];

__device__ int g_bsD[CSRB], g_bsS[CSRB], g_offD[CSRB], g_offS[CSRB];
__device__ int g_blkCntG[2][GB];
__device__ unsigned long long g_seedkeyG[2];
__device__ int g_hstarG[2], g_rremG[2], g_pstarG[2], g_pselBlockG[2], g_pselRemG[2];

__device__ unsigned g_barC = 0;
__device__ unsigned g_barG[2] = {0, 0};
__device__ unsigned g_ctrMega = 0;
__device__ unsigned g_ctrLoss = 0;

// ============================================================================
// helpers
// ============================================================================

__device__ __forceinline__ void xsync(unsigned* ctr, unsigned nblk, unsigned& epoch) {
    __syncthreads();
    if (threadIdx.x == 0) {
        __threadfence();
        unsigned target = (epoch + 1) * nblk;
        atomicAdd(ctr, 1u);
        while (*((volatile unsigned*)ctr) < target) {}
        __threadfence();
    }
    epoch++;
    __syncthreads();
}

__device__ __forceinline__ void xexit(unsigned* ctr, unsigned nblk, unsigned epoch) {
    __syncthreads();
    if (threadIdx.x == 0) {
        __threadfence();
        unsigned target = (epoch + 1) * nblk;
        if (atomicAdd(ctr, 1u) + 1 == target) *ctr = 0;
    }
}

__device__ __forceinline__ float softplusf(float x) {
    return fmaxf(x, 0.f) + log1pf(expf(-fabsf(x)));
}

__device__ __forceinline__ unsigned long long ullmin2(unsigned long long a, unsigned long long b) {
    return a < b ? a : b;
}

__device__ __forceinline__ int blockScanInc(int v, int* sWarp) {
    int lane = threadIdx.x & 31;
    int wid = threadIdx.x >> 5;
#pragma unroll
    for (int off = 1; off < 32; off <<= 1) {
        int t = __shfl_up_sync(0xffffffffu, v, off);
        if (lane >= off) v += t;
    }
    if (lane == 31) sWarp[wid] = v;
    __syncthreads();
    if (wid == 0) {
        int w = sWarp[lane];
#pragma unroll
        for (int off = 1; off < 32; off <<= 1) {
            int t = __shfl_up_sync(0xffffffffu, w, off);
            if (lane >= off) w += t;
        }
        sWarp[lane] = w;
    }
    __syncthreads();
    return v + (wid ? sWarp[wid - 1] : 0);
}

// ============================================================================
// Kernel 1: dual CSR build + feat->fp16 (+ permuted neg table) + zeroing
// ============================================================================

__global__ __launch_bounds__(1024, 2)
void csr_kernel(const float* __restrict__ feat, const int* __restrict__ src,
                const int* __restrict__ dst, const int* __restrict__ permneg,
                int e, int n) {
    unsigned epoch = 0;
    int gtid = blockIdx.x * 1024 + threadIdx.x;
    int gsz = gridDim.x * 1024;

    for (int i = gtid; i < n; i += gsz) { g_cntD[i] = 0; g_cntS[i] = 0; g_curD[i] = 0; g_curS[i] = 0; }
    if (gtid < 4) g_loss[gtid] = 0.0;
    if (gtid < 128) g_summary[gtid] = 0.0;
    if (gtid == 0) { g_rowD[n] = e; g_rowS[n] = e; }
    {
        int tot = n * 32;
        const float2* f2 = reinterpret_cast<const float2*>(feat);
        __half2* h2 = reinterpret_cast<__half2*>(g_feat16);
        for (int i = gtid; i < tot; i += gsz) h2[i] = __float22half2_rn(f2[i]);
    }
    xsync(&g_barC, gridDim.x, epoch);

    // counts + permuted neg feature table (feat16 now ready)
    for (int i = gtid; i < e; i += gsz) {
        atomicAdd(&g_cntD[dst[i]], 1);
        atomicAdd(&g_cntS[src[i]], 1);
    }
    {
        // featneg16[i] = feat16[permneg[i]]; warp per row-pair for coalescing
        int warp = gtid >> 5, lane = gtid & 31, nw = gsz >> 5;
        const __half2* fsrc = reinterpret_cast<const __half2*>(g_feat16);
        __half2* fdst = reinterpret_cast<__half2*>(g_featneg16);
        for (int i = warp; i < n; i += nw) {
            int r = __ldg(&permneg[i]);
            fdst[(size_t)i * 32 + lane] = fsrc[(size_t)r * 32 + lane];
        }
    }
    xsync(&g_barC, gridDim.x, epoch);

    __shared__ int sWarp[32];
    __shared__ int sRun, sTot;
    int chunk = (n + gridDim.x - 1) / gridDim.x;
    int b0 = blockIdx.x * chunk;
    int b1 = min(b0 + chunk, n);
    for (int which = 0; which < 2; which++) {
        int* cnt = which ? g_cntS : g_cntD;
        int* row = which ? g_rowS : g_rowD;
        int* bs = which ? g_bsS : g_bsD;
        if (threadIdx.x == 0) sRun = 0;
        __syncthreads();
        for (int base = b0; base < b1; base += 1024) {
            int i = base + threadIdx.x;
            int v = (i < b1) ? __ldcg(&cnt[i]) : 0;
            int incl = blockScanInc(v, sWarp);
            if (i < b1) row[i] = sRun + incl - v;
            if (threadIdx.x == 1023) sTot = incl;
            __syncthreads();
            if (threadIdx.x == 0) sRun += sTot;
            __syncthreads();
        }
        if (threadIdx.x == 0) bs[blockIdx.x] = sRun;
        __syncthreads();
    }
    xsync(&g_barC, gridDim.x, epoch);

    if (blockIdx.x == 0) {
        int b = threadIdx.x;
        int vD = (b < (int)gridDim.x) ? __ldcg(&g_bsD[b]) : 0;
        int incl = blockScanInc(vD, sWarp);
        if (b < (int)gridDim.x) g_offD[b] = incl - vD;
        int vS = (b < (int)gridDim.x) ? __ldcg(&g_bsS[b]) : 0;
        incl = blockScanInc(vS, sWarp);
        if (b < (int)gridDim.x) g_offS[b] = incl - vS;
    }
    xsync(&g_barC, gridDim.x, epoch);

    {
        int oD = __ldcg(&g_offD[blockIdx.x]);
        int oS = __ldcg(&g_offS[blockIdx.x]);
        for (int i = b0 + threadIdx.x; i < b1; i += 1024) {
            g_rowD[i] = __ldcg(&g_rowD[i]) + oD;
            g_rowS[i] = __ldcg(&g_rowS[i]) + oS;
        }
    }
    xsync(&g_barC, gridDim.x, epoch);

    for (int i = gtid; i < e; i += gsz) {
        int d = dst[i], s = src[i];
        int pd = atomicAdd(&g_curD[d], 1);
        g_colD[__ldcg(&g_rowD[d]) + pd] = (unsigned)s;
        int ps = atomicAdd(&g_curS[s], 1);
        g_colS[__ldcg(&g_rowS[s]) + ps] = d;
    }
    xexit(&g_barC, gridDim.x, epoch);
}

// ============================================================================
// Kernel 2: dual frontier-BFS + exact top-k selection (both perms concurrent)
// ============================================================================

__global__ __launch_bounds__(1024, 1)
void bfs_dual_kernel(const int* __restrict__ perm1, const int* __restrict__ perm2, int n, int k) {
    int g = (blockIdx.x < GB) ? 0 : 1;
    int gb = blockIdx.x - g * GB;
    const int* perm = g ? perm2 : perm1;
    unsigned char* keep = g ? g_keep2 : g_keep1;
    int* hop = g_hopG[g];
    int* invp = g_invpermG[g];
    int* hist = g_histG[g];
    unsigned* bar = &g_barG[g];
    unsigned epoch = 0;
    int gtid = gb * 1024 + threadIdx.x;
    int gsz = GB * 1024;
    const int INF = n;

    __shared__ int sWarp[32];
    __shared__ unsigned long long sK[32];

    int root = __ldg(&perm[0]);
    for (int i = gtid; i < n; i += gsz) {
        __stcg(&hop[i], (i == root) ? 0 : INF);
        __stcg(&invp[__ldg(&perm[i])], i);
    }
    for (int i = gtid; i < HIST_BINS; i += gsz) __stcg(&hist[i], 0);
    for (int i = gtid; i < MAX_SWEEPS + 8; i += gsz) __stcg(&g_szHist[g][i], 0);
    if (gtid == 0) {
        __stcg(&g_front[g][0][0], root);
        __stcg(&g_szHist[g][0], 1);
        g_seedkeyG[g] = ~0ull;
    }
    xsync(bar, GB, epoch);

    int cnt = 1;
    int t = 0;
    int lane = threadIdx.x & 31;
    while (cnt <= k && t < MAX_SWEEPS) {
        int fsz = __ldcg(&g_szHist[g][t]);
        const int* fin = g_front[g][t & 1];
        int* fout = g_front[g][(t + 1) & 1];
        int* ctr = &g_szHist[g][t + 1];
        for (int idx = gtid; idx < fsz; idx += gsz) {
            int u = __ldcg(&fin[idx]);
            int s0 = g_rowS[u], s1 = g_rowS[u + 1];
            for (int e2 = s0; e2 < s1; e2++) {
                int v = g_colS[e2];
                bool win = false;
                if (__ldcg(&hop[v]) == INF)
                    win = (atomicCAS(&hop[v], INF, t + 1) == INF);
                if (win) {
                    cg::coalesced_group grp = cg::coalesced_threads();
                    int base;
                    if (grp.thread_rank() == 0) base = atomicAdd(ctr, (int)grp.size());
                    base = grp.shfl(base, 0);
                    __stcg(&fout[base + grp.thread_rank()], v);
                }
            }
        }
        xsync(bar, GB, epoch);
        int newly = __ldcg(&g_szHist[g][t + 1]);
        t += 1;
        cnt += newly;
        if (newly == 0 && cnt <= k) {
            unsigned long long key = ~0ull;
            for (int i = gtid; i < n; i += gsz) {
                if (__ldcg(&hop[i]) == INF)
                    key = ullmin2(key, ((unsigned long long)(unsigned)__ldg(&perm[i]) << 32) | (unsigned)i);
            }
#pragma unroll
            for (int off = 16; off; off >>= 1)
                key = ullmin2(key, __shfl_down_sync(0xffffffffu, key, off));
            int wid = threadIdx.x >> 5;
            if (lane == 0) sK[wid] = key;
            __syncthreads();
            if (threadIdx.x < 32) {
                unsigned long long kk2 = sK[threadIdx.x];
#pragma unroll
                for (int off = 16; off; off >>= 1)
                    kk2 = ullmin2(kk2, __shfl_down_sync(0xffffffffu, kk2, off));
                if (threadIdx.x == 0 && kk2 != ~0ull) atomicMin(&g_seedkeyG[g], kk2);
            }
            xsync(bar, GB, epoch);
            if (gtid == 0) {
                unsigned long long kv = g_seedkeyG[g];
                int idx = (int)(unsigned)(kv & 0xffffffffull);
                __stcg(&hop[idx], t);
                __stcg(&g_front[g][t & 1][0], idx);
                __stcg(&g_szHist[g][t], 1);
                g_seedkeyG[g] = ~0ull;
            }
            cnt += 1;
            xsync(bar, GB, epoch);
        }
    }

    {
        __shared__ int sh[256];
        for (int j = threadIdx.x; j < 256; j += 1024) sh[j] = 0;
        __syncthreads();
        for (int i = gtid; i < n; i += gsz) {
            int hv = min(__ldcg(&hop[i]), 15000);
            if (hv < 256) atomicAdd(&sh[hv], 1);
            else atomicAdd(&hist[hv], 1);
        }
        __syncthreads();
        for (int j = threadIdx.x; j < 256; j += 1024)
            if (sh[j]) atomicAdd(&hist[j], sh[j]);
    }
    xsync(bar, GB, epoch);

    if (gb == 0) {
        __shared__ int sRun, sTot, sDone;
        if (threadIdx.x == 0) { sRun = 0; sDone = 0; }
        __syncthreads();
        for (int base = 0; base < HIST_BINS; base += 1024) {
            if (sDone) break;
            int h = base + threadIdx.x;
            int v = (h < HIST_BINS) ? __ldcg(&hist[h]) : 0;
            int incl = blockScanInc(v, sWarp);
            int P = sRun + incl;
            if (v > 0 && P >= k && P - v < k) { g_hstarG[g] = h; g_rremG[g] = k - (P - v); sDone = 1; }
            if (threadIdx.x == 1023) sTot = incl;
            __syncthreads();
            if (threadIdx.x == 0) sRun += sTot;
            __syncthreads();
        }
    }
    xsync(bar, GB, epoch);
    int hstar = *(volatile int*)&g_hstarG[g];
    int rrem = *(volatile int*)&g_rremG[g];

    int chunk = (n + GB - 1) / GB;
    int v0 = gb * chunk, v1 = min(v0 + chunk, n);
    {
        int c = 0;
        for (int v = v0 + threadIdx.x; v < v1; v += 1024) {
            int j = __ldcg(&invp[v]);
            c += (min(__ldcg(&hop[j]), 15000) == hstar);
        }
#pragma unroll
        for (int off = 16; off; off >>= 1) c += __shfl_down_sync(0xffffffffu, c, off);
        int wid = threadIdx.x >> 5;
        if (lane == 0) sWarp[wid] = c;
        __syncthreads();
        if (threadIdx.x < 32) {
            int r = sWarp[threadIdx.x];
#pragma unroll
            for (int off = 16; off; off >>= 1) r += __shfl_down_sync(0xffffffffu, r, off);
            if (threadIdx.x == 0) g_blkCntG[g][gb] = r;
        }
    }
    xsync(bar, GB, epoch);
    if (gb == 0) {
        int b = threadIdx.x;
        int v = (b < GB) ? __ldcg(&g_blkCntG[g][b]) : 0;
        int incl = blockScanInc(v, sWarp);
        int excl = incl - v;
        if (b < GB && v > 0 && excl < rrem && rrem <= incl) {
            g_pselBlockG[g] = b; g_pselRemG[g] = rrem - excl;
        }
    }
    xsync(bar, GB, epoch);
    if (gb == *(volatile int*)&g_pselBlockG[g]) {
        int rem = *(volatile int*)&g_pselRemG[g];
        __shared__ int sRun2, sTot2, sDone2;
        if (threadIdx.x == 0) { sRun2 = 0; sDone2 = 0; }
        __syncthreads();
        for (int base = v0; base < v1; base += 1024) {
            if (sDone2) break;
            int v = base + threadIdx.x;
            int pred = 0;
            if (v < v1) {
                int j = __ldcg(&invp[v]);
                pred = (min(__ldcg(&hop[j]), 15000) == hstar);
            }
            int incl = blockScanInc(pred, sWarp);
            int cum = sRun2 + incl;
            if (pred && cum == rem) { g_pstarG[g] = v; sDone2 = 1; }
            if (threadIdx.x == 1023) sTot2 = incl;
            __syncthreads();
            if (threadIdx.x == 0) sRun2 += sTot2;
            __syncthreads();
        }
    }
    xsync(bar, GB, epoch);
    int pstar = *(volatile int*)&g_pstarG[g];
    for (int i = gtid; i < n; i += gsz) {
        int hv = min(__ldcg(&hop[i]), 15000);
        keep[i] = (hv < hstar) || (hv == hstar && __ldg(&perm[i]) <= pstar);
    }
    xexit(bar, GB, epoch);
}

// ============================================================================
// Kernel 3: annotate colD with source keep bits (bit30 = keep1, bit31 = keep2)
// ============================================================================

__global__ __launch_bounds__(1024)
void annotate_kernel(int e) {
    int i = blockIdx.x * 1024 + threadIdx.x;
    int gsz = gridDim.x * 1024;
    for (; i < e; i += gsz) {
        unsigned c = g_colD[i] & 0x3FFFFFFFu;
        unsigned k1 = (unsigned)g_keep1[c];
        unsigned k2 = (unsigned)g_keep2[c];
        g_colD[i] = c | (k1 << 30) | (k2 << 31);
    }
}

// ============================================================================
// Kernel 4: mega GCN — pos+neg+mask1+mask2 from annotated colD, 4-edge unroll,
// 2 nodes/warp tiled GEMV, fp16 h output; LAST block computes v.
// ============================================================================

__global__ __launch_bounds__(256)
void mega_gcn_kernel(const float* __restrict__ Wenc, const float* __restrict__ Wdisc,
                     int n, int k) {
    __shared__ float sW[4096];
    __shared__ float sxp[8][64][2];
    __shared__ float sxn[8][64][2];
    __shared__ float sx1[8][64][2];
    __shared__ float sx2[8][64][2];
    __shared__ double sSum[128];
    __shared__ int sLast;
    int tid = threadIdx.x;
    for (int j = tid; j < 4096; j += 256) sW[j] = Wenc[j];
    if (tid < 128) sSum[tid] = 0.0;
    __syncthreads();
    int warp = tid >> 5, lane = tid & 31;
    double A10 = 0.0, A11 = 0.0, A20 = 0.0, A21 = 0.0;
    const __half2* FP = reinterpret_cast<const __half2*>(g_feat16);
    const __half2* FN = reinterpret_cast<const __half2*>(g_featneg16);

    for (int nb = (blockIdx.x * 8 + warp) * 2; nb < n; nb += gridDim.x * 16) {
        int k1d[2], k2d[2];
#pragma unroll
        for (int j = 0; j < 2; j++) {
            int node = nb + j;
            bool valid = node < n;
            k1d[j] = valid ? (int)g_keep1[node] : 0;
            k2d[j] = valid ? (int)g_keep2[node] : 0;
            int s0 = valid ? g_rowD[node] : 0;
            int s1 = valid ? g_rowD[node + 1] : 0;

            float p0 = 0.f, p1 = 0.f, q0 = 0.f, q1 = 0.f;
            float m10 = 0.f, m11 = 0.f, m20 = 0.f, m21 = 0.f;
            int c1 = 0, c2 = 0;

            int e2 = s0;
            for (; e2 + 4 <= s1; e2 += 4) {
                unsigned cA = __ldcs(&g_colD[e2]);
                unsigned cB = __ldcs(&g_colD[e2 + 1]);
                unsigned cC = __ldcs(&g_colD[e2 + 2]);
                unsigned cD = __ldcs(&g_colD[e2 + 3]);
                unsigned sA = cA & 0x3FFFFFFFu, sB = cB & 0x3FFFFFFFu;
                unsigned sC = cC & 0x3FFFFFFFu, sD = cD & 0x3FFFFFFFu;
                // 8 independent row loads in flight
                float2 fA = __half22float2(FP[(size_t)sA * 32 + lane]);
                float2 fB = __half22float2(FP[(size_t)sB * 32 + lane]);
                float2 fC = __half22float2(FP[(size_t)sC * 32 + lane]);
                float2 fD = __half22float2(FP[(size_t)sD * 32 + lane]);
                float2 gA = __half22float2(FN[(size_t)sA * 32 + lane]);
                float2 gB2 = __half22float2(FN[(size_t)sB * 32 + lane]);
                float2 gC = __half22float2(FN[(size_t)sC * 32 + lane]);
                float2 gD = __half22float2(FN[(size_t)sD * 32 + lane]);
                p0 += (fA.x + fB.x) + (fC.x + fD.x);
                p1 += (fA.y + fB.y) + (fC.y + fD.y);
                q0 += (gA.x + gB2.x) + (gC.x + gD.x);
                q1 += (gA.y + gB2.y) + (gC.y + gD.y);
                int kA1 = k1d[j] & (int)(cA >> 30) & 1, kB1 = k1d[j] & (int)(cB >> 30) & 1;
                int kC1 = k1d[j] & (int)(cC >> 30) & 1, kD1 = k1d[j] & (int)(cD >> 30) & 1;
                int kA2 = k2d[j] & (int)(cA >> 31), kB2 = k2d[j] & (int)(cB >> 31);
                int kC2 = k2d[j] & (int)(cC >> 31), kD2 = k2d[j] & (int)(cD >> 31);
                m10 += fA.x * (float)kA1 + fB.x * (float)kB1 + fC.x * (float)kC1 + fD.x * (float)kD1;
                m11 += fA.y * (float)kA1 + fB.y * (float)kB1 + fC.y * (float)kC1 + fD.y * (float)kD1;
                m20 += fA.x * (float)kA2 + fB.x * (float)kB2 + fC.x * (float)kC2 + fD.x * (float)kD2;
                m21 += fA.y * (float)kA2 + fB.y * (float)kB2 + fC.y * (float)kC2 + fD.y * (float)kD2;
                c1 += kA1 + kB1 + kC1 + kD1;
                c2 += kA2 + kB2 + kC2 + kD2;
            }
            for (; e2 < s1; e2++) {
                unsigned cA = __ldcs(&g_colD[e2]);
                unsigned sA = cA & 0x3FFFFFFFu;
                float2 fA = __half22float2(FP[(size_t)sA * 32 + lane]);
                float2 gA = __half22float2(FN[(size_t)sA * 32 + lane]);
                p0 += fA.x; p1 += fA.y; q0 += gA.x; q1 += gA.y;
                int kA1 = k1d[j] & (int)(cA >> 30) & 1;
                int kA2 = k2d[j] & (int)(cA >> 31);
                m10 += fA.x * (float)kA1; m11 += fA.y * (float)kA1;
                m20 += fA.x * (float)kA2; m21 += fA.y * (float)kA2;
                c1 += kA1; c2 += kA2;
            }

            float invd = 1.f / (float)max(s1 - s0, 1);
            float i1 = 1.f / (float)max(c1, 1);
            float i2 = 1.f / (float)max(c2, 1);
            sxp[warp][2 * lane][j] = p0 * invd; sxp[warp][2 * lane + 1][j] = p1 * invd;
            sxn[warp][2 * lane][j] = q0 * invd; sxn[warp][2 * lane + 1][j] = q1 * invd;
            sx1[warp][2 * lane][j] = m10 * i1;  sx1[warp][2 * lane + 1][j] = m11 * i1;
            sx2[warp][2 * lane][j] = m20 * i2;  sx2[warp][2 * lane + 1][j] = m21 * i2;
        }
        __syncwarp();

        float opa[2] = {0, 0}, opb[2] = {0, 0};
        float ona[2] = {0, 0}, onb[2] = {0, 0};
        float o1a[2] = {0, 0}, o1b[2] = {0, 0};
        float o2a[2] = {0, 0}, o2b[2] = {0, 0};
#pragma unroll 16
        for (int kk = 0; kk < 64; kk++) {
            float2 w = *reinterpret_cast<const float2*>(&sW[kk * 64 + 2 * lane]);
            float2 xp = *reinterpret_cast<const float2*>(&sxp[warp][kk][0]);
            float2 xn = *reinterpret_cast<const float2*>(&sxn[warp][kk][0]);
            float2 x1 = *reinterpret_cast<const float2*>(&sx1[warp][kk][0]);
            float2 x2 = *reinterpret_cast<const float2*>(&sx2[warp][kk][0]);
            opa[0] += xp.x * w.x; opb[0] += xp.x * w.y;
            opa[1] += xp.y * w.x; opb[1] += xp.y * w.y;
            ona[0] += xn.x * w.x; onb[0] += xn.x * w.y;
            ona[1] += xn.y * w.x; onb[1] += xn.y * w.y;
            o1a[0] += x1.x * w.x; o1b[0] += x1.x * w.y;
            o1a[1] += x1.y * w.x; o1b[1] += x1.y * w.y;
            o2a[0] += x2.x * w.x; o2b[0] += x2.x * w.y;
            o2a[1] += x2.y * w.x; o2b[1] += x2.y * w.y;
        }
#pragma unroll
        for (int j = 0; j < 2; j++) {
            int node = nb + j;
            if (node < n) {
                reinterpret_cast<__half2*>(g_hpos16)[(size_t)node * 32 + lane] =
                    __floats2half2_rn(fmaxf(opa[j], 0.f), fmaxf(opb[j], 0.f));
                reinterpret_cast<__half2*>(g_hneg16)[(size_t)node * 32 + lane] =
                    __floats2half2_rn(fmaxf(ona[j], 0.f), fmaxf(onb[j], 0.f));
                if (k1d[j]) { A10 += (double)fmaxf(o1a[j], 0.f); A11 += (double)fmaxf(o1b[j], 0.f); }
                if (k2d[j]) { A20 += (double)fmaxf(o2a[j], 0.f); A21 += (double)fmaxf(o2b[j], 0.f); }
            }
        }
        __syncwarp();
    }
    atomicAdd(&sSum[2 * lane], A10);
    atomicAdd(&sSum[2 * lane + 1], A11);
    atomicAdd(&sSum[64 + 2 * lane], A20);
    atomicAdd(&sSum[64 + 2 * lane + 1], A21);
    __syncthreads();
    if (tid < 128) {
        double v = sSum[tid];
        if (v != 0.0) atomicAdd(&g_summary[tid], v);
    }

    if (tid == 0) {
        __threadfence();
        sLast = (atomicAdd(&g_ctrMega, 1u) == gridDim.x - 1);
    }
    __syncthreads();
    if (sLast) {
        __shared__ float ss[2][64];
        if (tid < 128) {
            double s = g_summary[tid] / (double)k;
            ss[tid >> 6][tid & 63] = (float)(1.0 / (1.0 + exp(-s)));
        }
        __syncthreads();
        if (tid < 128) {
            int p = tid >> 6, c = tid & 63;
            float v = 0.f;
#pragma unroll
            for (int b = 0; b < 64; b++) v += Wdisc[c * 64 + b] * ss[p][b];
            g_v[p][c] = v;
        }
        if (tid == 0) g_ctrMega = 0;
    }
}

// ============================================================================
// Kernel 5: BCE losses (streams fp16 h); last block writes final output.
// ============================================================================

__global__ __launch_bounds__(256)
void loss_kernel(float* __restrict__ out, int n) {
    __shared__ float sv0[64], sv1[64];
    __shared__ double sL[4];
    __shared__ int sLast;
    int tid = threadIdx.x;
    if (tid < 64) { sv0[tid] = g_v[0][tid]; sv1[tid] = g_v[1][tid]; }
    if (tid < 4) sL[tid] = 0.0;
    __syncthreads();
    int warp = tid >> 5, lane = tid & 31;
    float v00 = sv0[2 * lane], v01 = sv0[2 * lane + 1];
    float v10 = sv1[2 * lane], v11 = sv1[2 * lane + 1];
    double l0 = 0, l1 = 0, l2 = 0, l3 = 0;
    const __half2* HP = reinterpret_cast<const __half2*>(g_hpos16);
    const __half2* HN = reinterpret_cast<const __half2*>(g_hneg16);
    for (int node = blockIdx.x * 8 + warp; node < n; node += gridDim.x * 8) {
        float2 hp = __half22float2(HP[(size_t)node * 32 + lane]);
        float2 hn = __half22float2(HN[(size_t)node * 32 + lane]);
        float p1 = hp.x * v00 + hp.y * v01;
        float p2 = hp.x * v10 + hp.y * v11;
        float q1 = hn.x * v00 + hn.y * v01;
        float q2 = hn.x * v10 + hn.y * v11;
#pragma unroll
        for (int off = 16; off; off >>= 1) {
            p1 += __shfl_down_sync(0xffffffffu, p1, off);
            p2 += __shfl_down_sync(0xffffffffu, p2, off);
            q1 += __shfl_down_sync(0xffffffffu, q1, off);
            q2 += __shfl_down_sync(0xffffffffu, q2, off);
        }
        if (lane == 0) {
            l0 += (double)softplusf(-p1);
            l1 += (double)softplusf(q1);
            l2 += (double)softplusf(-p2);
            l3 += (double)softplusf(q2);
        }
    }
    if (lane == 0) {
        atomicAdd(&sL[0], l0); atomicAdd(&sL[1], l1);
        atomicAdd(&sL[2], l2); atomicAdd(&sL[3], l3);
    }
    __syncthreads();
    if (tid < 4) atomicAdd(&g_loss[tid], sL[tid]);

    if (tid == 0) {
        __threadfence();
        sLast = (atomicAdd(&g_ctrLoss, 1u) == gridDim.x - 1);
    }
    __syncthreads();
    if (sLast && tid == 0) {
        out[0] = (float)((g_loss[0] + g_loss[1] + g_loss[2] + g_loss[3]) / (double)n);
        g_ctrLoss = 0;
    }
}

// ============================================================================
// launch
// ============================================================================

extern "C" void kernel_launch(void* const* d_in, const int* in_sizes, int n_in,
                              void* d_out, int out_size) {
    const float* feat = (const float*)d_in[0];
    const float* Wenc = (const float*)d_in[1];
    const float* Wdisc = (const float*)d_in[2];
    const int* src = (const int*)d_in[3];
    const int* dst = (const int*)d_in[4];
    const int* permneg = (const int*)d_in[5];
    const int* perm1 = (const int*)d_in[6];
    const int* perm2 = (const int*)d_in[7];

    int e = in_sizes[3];
    int n = in_sizes[5];
    int k = (int)((double)n * 0.8);

    csr_kernel<<<CSRB, 1024>>>(feat, src, dst, permneg, e, n);
    bfs_dual_kernel<<<BFSB, 1024>>>(perm1, perm2, n, k);
    annotate_kernel<<<264, 1024>>>(e);

    int mGrid = (n + 15) / 16;
    if (mGrid > 1480) mGrid = 1480;
    mega_gcn_kernel<<<mGrid, 256>>>(Wenc, Wdisc, n, k);

    int lGrid = (n + 7) / 8;
    if (lGrid > 1480) lGrid = 1480;
    loss_kernel<<<lGrid, 256>>>((float*)d_out, n);
}

// round 9
// speedup vs baseline: 1.2636x; 1.0352x over previous
#include <cuda_runtime.h>
#include <cuda_fp16.h>
#include <cooperative_groups.h>
#include <math.h>

namespace cg = cooperative_groups;

// ============================================================================
// DGISubgraphCL — 5-launch pipeline:
//   csr (dual CSR + fp16 feat + permuted neg feat) -> dual frontier-BFS +
//   top-k -> annotate (keep bits into colD) -> mega GCN (4 aggregations, one
//   gather pass, f32x2 packed GEMV; last block computes v) -> loss (fp16 h).
// ============================================================================

#define N_MAX 131072
#define E_MAX (N_MAX * 17)
#define HIST_BINS 15001
#define CSRB 264
#define BFSB 132
#define GB 66
#define MAX_SWEEPS 250

typedef unsigned long long ull;

// ---- device scratch ----
__device__ int g_rowD[N_MAX + 1], g_cntD[N_MAX], g_curD[N_MAX];
__device__ int g_rowS[N_MAX + 1], g_cntS[N_MAX], g_curS[N_MAX];
__device__ unsigned g_colD[E_MAX];          // after annotate: s | k1<<30 | k2<<31
__device__ int g_colS[E_MAX];
__device__ __half g_feat16[(size_t)N_MAX * 64];
__device__ __half g_featneg16[(size_t)N_MAX * 64];
__device__ int g_hopG[2][N_MAX];
__device__ int g_front[2][2][N_MAX];
__device__ int g_invpermG[2][N_MAX];
__device__ int g_histG[2][HIST_BINS];
__device__ int g_szHist[2][MAX_SWEEPS + 8];
__device__ unsigned char g_keep1[N_MAX];
__device__ unsigned char g_keep2[N_MAX];
__device__ __half g_hpos16[(size_t)N_MAX * 64];
__device__ __half g_hneg16[(size_t)N_MAX * 64];
__device__ double g_summary[128];
__device__ float g_v[2][64];
__device__ double g_loss[4];

__device__ int g_bsD[CSRB], g_bsS[CSRB], g_offD[CSRB], g_offS[CSRB];
__device__ int g_blkCntG[2][GB];
__device__ unsigned long long g_seedkeyG[2];
__device__ int g_hstarG[2], g_rremG[2], g_pstarG[2], g_pselBlockG[2], g_pselRemG[2];

__device__ unsigned g_barC = 0;
__device__ unsigned g_barG[2] = {0, 0};
__device__ unsigned g_ctrMega = 0;
__device__ unsigned g_ctrLoss = 0;

// ============================================================================
// helpers
// ============================================================================

__device__ __forceinline__ ull pack2(float x, float y) {
    ull r; asm("mov.b64 %0, {%1, %2};" : "=l"(r) : "f"(x), "f"(y)); return r;
}
__device__ __forceinline__ void unpack2(ull v, float& x, float& y) {
    asm("mov.b64 {%0, %1}, %2;" : "=f"(x), "=f"(y) : "l"(v));
}
__device__ __forceinline__ ull fma2(ull a, ull b, ull c) {
    ull d; asm("fma.rn.f32x2 %0, %1, %2, %3;" : "=l"(d) : "l"(a), "l"(b), "l"(c)); return d;
}

__device__ __forceinline__ void xsync(unsigned* ctr, unsigned nblk, unsigned& epoch) {
    __syncthreads();
    if (threadIdx.x == 0) {
        __threadfence();
        unsigned target = (epoch + 1) * nblk;
        atomicAdd(ctr, 1u);
        while (*((volatile unsigned*)ctr) < target) {}
        __threadfence();
    }
    epoch++;
    __syncthreads();
}

__device__ __forceinline__ void xexit(unsigned* ctr, unsigned nblk, unsigned epoch) {
    __syncthreads();
    if (threadIdx.x == 0) {
        __threadfence();
        unsigned target = (epoch + 1) * nblk;
        if (atomicAdd(ctr, 1u) + 1 == target) *ctr = 0;
    }
}

__device__ __forceinline__ float softplusf(float x) {
    return fmaxf(x, 0.f) + log1pf(expf(-fabsf(x)));
}

__device__ __forceinline__ unsigned long long ullmin2(unsigned long long a, unsigned long long b) {
    return a < b ? a : b;
}

__device__ __forceinline__ int blockScanInc(int v, int* sWarp) {
    int lane = threadIdx.x & 31;
    int wid = threadIdx.x >> 5;
#pragma unroll
    for (int off = 1; off < 32; off <<= 1) {
        int t = __shfl_up_sync(0xffffffffu, v, off);
        if (lane >= off) v += t;
    }
    if (lane == 31) sWarp[wid] = v;
    __syncthreads();
    if (wid == 0) {
        int w = sWarp[lane];
#pragma unroll
        for (int off = 1; off < 32; off <<= 1) {
            int t = __shfl_up_sync(0xffffffffu, w, off);
            if (lane >= off) w += t;
        }
        sWarp[lane] = w;
    }
    __syncthreads();
    return v + (wid ? sWarp[wid - 1] : 0);
}

// ============================================================================
// Kernel 1: dual CSR build + feat->fp16 (+ permuted neg table) + zeroing
// ============================================================================

__global__ __launch_bounds__(1024, 2)
void csr_kernel(const float* __restrict__ feat, const int* __restrict__ src,
                const int* __restrict__ dst, const int* __restrict__ permneg,
                int e, int n) {
    unsigned epoch = 0;
    int gtid = blockIdx.x * 1024 + threadIdx.x;
    int gsz = gridDim.x * 1024;

    for (int i = gtid; i < n; i += gsz) { g_cntD[i] = 0; g_cntS[i] = 0; }
    if (gtid < 4) g_loss[gtid] = 0.0;
    if (gtid < 128) g_summary[gtid] = 0.0;
    if (gtid == 0) { g_rowD[n] = e; g_rowS[n] = e; }
    {
        int tot = n * 32;
        const float2* f2 = reinterpret_cast<const float2*>(feat);
        __half2* h2 = reinterpret_cast<__half2*>(g_feat16);
        for (int i = gtid; i < tot; i += gsz) h2[i] = __float22half2_rn(f2[i]);
    }
    xsync(&g_barC, gridDim.x, epoch);

    for (int i = gtid; i < e; i += gsz) {
        atomicAdd(&g_cntD[dst[i]], 1);
        atomicAdd(&g_cntS[src[i]], 1);
    }
    {
        // featneg16[i] = feat16[permneg[i]]; warp per row for coalescing
        int warp = gtid >> 5, lane = gtid & 31, nw = gsz >> 5;
        const __half2* fsrc = reinterpret_cast<const __half2*>(g_feat16);
        __half2* fdst = reinterpret_cast<__half2*>(g_featneg16);
        for (int i = warp; i < n; i += nw) {
            int r = __ldg(&permneg[i]);
            fdst[(size_t)i * 32 + lane] = fsrc[(size_t)r * 32 + lane];
        }
    }
    xsync(&g_barC, gridDim.x, epoch);

    __shared__ int sWarp[32];
    __shared__ int sRun, sTot;
    int chunk = (n + gridDim.x - 1) / gridDim.x;
    int b0 = blockIdx.x * chunk;
    int b1 = min(b0 + chunk, n);
    for (int which = 0; which < 2; which++) {
        int* cnt = which ? g_cntS : g_cntD;
        int* row = which ? g_rowS : g_rowD;
        int* bs = which ? g_bsS : g_bsD;
        if (threadIdx.x == 0) sRun = 0;
        __syncthreads();
        for (int base = b0; base < b1; base += 1024) {
            int i = base + threadIdx.x;
            int v = (i < b1) ? __ldcg(&cnt[i]) : 0;
            int incl = blockScanInc(v, sWarp);
            if (i < b1) row[i] = sRun + incl - v;
            if (threadIdx.x == 1023) sTot = incl;
            __syncthreads();
            if (threadIdx.x == 0) sRun += sTot;
            __syncthreads();
        }
        if (threadIdx.x == 0) bs[blockIdx.x] = sRun;
        __syncthreads();
    }
    xsync(&g_barC, gridDim.x, epoch);

    if (blockIdx.x == 0) {
        int b = threadIdx.x;
        int vD = (b < (int)gridDim.x) ? __ldcg(&g_bsD[b]) : 0;
        int incl = blockScanInc(vD, sWarp);
        if (b < (int)gridDim.x) g_offD[b] = incl - vD;
        int vS = (b < (int)gridDim.x) ? __ldcg(&g_bsS[b]) : 0;
        incl = blockScanInc(vS, sWarp);
        if (b < (int)gridDim.x) g_offS[b] = incl - vS;
    }
    xsync(&g_barC, gridDim.x, epoch);

    {
        int oD = __ldcg(&g_offD[blockIdx.x]);
        int oS = __ldcg(&g_offS[blockIdx.x]);
        for (int i = b0 + threadIdx.x; i < b1; i += 1024) {
            int vD = __ldcg(&g_rowD[i]) + oD;
            int vS = __ldcg(&g_rowS[i]) + oS;
            g_rowD[i] = vD; g_curD[i] = vD;     // cursor starts at row base
            g_rowS[i] = vS; g_curS[i] = vS;
        }
    }
    xsync(&g_barC, gridDim.x, epoch);

    // scatter: single atomic gives absolute slot (no rowptr gather)
    for (int i = gtid; i < e; i += gsz) {
        int d = dst[i], s = src[i];
        int pd = atomicAdd(&g_curD[d], 1);
        g_colD[pd] = (unsigned)s;
        int ps = atomicAdd(&g_curS[s], 1);
        g_colS[ps] = d;
    }
    xexit(&g_barC, gridDim.x, epoch);
}

// ============================================================================
// Kernel 2: dual frontier-BFS + exact top-k selection (both perms concurrent)
// ============================================================================

__global__ __launch_bounds__(1024, 1)
void bfs_dual_kernel(const int* __restrict__ perm1, const int* __restrict__ perm2, int n, int k) {
    int g = (blockIdx.x < GB) ? 0 : 1;
    int gb = blockIdx.x - g * GB;
    const int* perm = g ? perm2 : perm1;
    unsigned char* keep = g ? g_keep2 : g_keep1;
    int* hop = g_hopG[g];
    int* invp = g_invpermG[g];
    int* hist = g_histG[g];
    unsigned* bar = &g_barG[g];
    unsigned epoch = 0;
    int gtid = gb * 1024 + threadIdx.x;
    int gsz = GB * 1024;
    const int INF = n;

    __shared__ int sWarp[32];
    __shared__ unsigned long long sK[32];

    int root = __ldg(&perm[0]);
    for (int i = gtid; i < n; i += gsz) {
        __stcg(&hop[i], (i == root) ? 0 : INF);
        __stcg(&invp[__ldg(&perm[i])], i);
    }
    for (int i = gtid; i < HIST_BINS; i += gsz) __stcg(&hist[i], 0);
    for (int i = gtid; i < MAX_SWEEPS + 8; i += gsz) __stcg(&g_szHist[g][i], 0);
    if (gtid == 0) {
        __stcg(&g_front[g][0][0], root);
        __stcg(&g_szHist[g][0], 1);
        g_seedkeyG[g] = ~0ull;
    }
    xsync(bar, GB, epoch);

    int cnt = 1;
    int t = 0;
    int lane = threadIdx.x & 31;
    while (cnt <= k && t < MAX_SWEEPS) {
        int fsz = __ldcg(&g_szHist[g][t]);
        const int* fin = g_front[g][t & 1];
        int* fout = g_front[g][(t + 1) & 1];
        int* ctr = &g_szHist[g][t + 1];
        for (int idx = gtid; idx < fsz; idx += gsz) {
            int u = __ldcg(&fin[idx]);
            int s0 = g_rowS[u], s1 = g_rowS[u + 1];
            for (int e2 = s0; e2 < s1; e2++) {
                int v = g_colS[e2];
                bool win = false;
                if (__ldcg(&hop[v]) == INF)
                    win = (atomicCAS(&hop[v], INF, t + 1) == INF);
                if (win) {
                    cg::coalesced_group grp = cg::coalesced_threads();
                    int base;
                    if (grp.thread_rank() == 0) base = atomicAdd(ctr, (int)grp.size());
                    base = grp.shfl(base, 0);
                    __stcg(&fout[base + grp.thread_rank()], v);
                }
            }
        }
        xsync(bar, GB, epoch);
        int newly = __ldcg(&g_szHist[g][t + 1]);
        t += 1;
        cnt += newly;
        if (newly == 0 && cnt <= k) {
            unsigned long long key = ~0ull;
            for (int i = gtid; i < n; i += gsz) {
                if (__ldcg(&hop[i]) == INF)
                    key = ullmin2(key, ((unsigned long long)(unsigned)__ldg(&perm[i]) << 32) | (unsigned)i);
            }
#pragma unroll
            for (int off = 16; off; off >>= 1)
                key = ullmin2(key, __shfl_down_sync(0xffffffffu, key, off));
            int wid = threadIdx.x >> 5;
            if (lane == 0) sK[wid] = key;
            __syncthreads();
            if (threadIdx.x < 32) {
                unsigned long long kk2 = sK[threadIdx.x];
#pragma unroll
                for (int off = 16; off; off >>= 1)
                    kk2 = ullmin2(kk2, __shfl_down_sync(0xffffffffu, kk2, off));
                if (threadIdx.x == 0 && kk2 != ~0ull) atomicMin(&g_seedkeyG[g], kk2);
            }
            xsync(bar, GB, epoch);
            if (gtid == 0) {
                unsigned long long kv = g_seedkeyG[g];
                int idx = (int)(unsigned)(kv & 0xffffffffull);
                __stcg(&hop[idx], t);
                __stcg(&g_front[g][t & 1][0], idx);
                __stcg(&g_szHist[g][t], 1);
                g_seedkeyG[g] = ~0ull;
            }
            cnt += 1;
            xsync(bar, GB, epoch);
        }
    }

    {
        __shared__ int sh[256];
        for (int j = threadIdx.x; j < 256; j += 1024) sh[j] = 0;
        __syncthreads();
        for (int i = gtid; i < n; i += gsz) {
            int hv = min(__ldcg(&hop[i]), 15000);
            if (hv < 256) atomicAdd(&sh[hv], 1);
            else atomicAdd(&hist[hv], 1);
        }
        __syncthreads();
        for (int j = threadIdx.x; j < 256; j += 1024)
            if (sh[j]) atomicAdd(&hist[j], sh[j]);
    }
    xsync(bar, GB, epoch);

    if (gb == 0) {
        __shared__ int sRun, sTot, sDone;
        if (threadIdx.x == 0) { sRun = 0; sDone = 0; }
        __syncthreads();
        for (int base = 0; base < HIST_BINS; base += 1024) {
            if (sDone) break;
            int h = base + threadIdx.x;
            int v = (h < HIST_BINS) ? __ldcg(&hist[h]) : 0;
            int incl = blockScanInc(v, sWarp);
            int P = sRun + incl;
            if (v > 0 && P >= k && P - v < k) { g_hstarG[g] = h; g_rremG[g] = k - (P - v); sDone = 1; }
            if (threadIdx.x == 1023) sTot = incl;
            __syncthreads();
            if (threadIdx.x == 0) sRun += sTot;
            __syncthreads();
        }
    }
    xsync(bar, GB, epoch);
    int hstar = *(volatile int*)&g_hstarG[g];
    int rrem = *(volatile int*)&g_rremG[g];

    int chunk = (n + GB - 1) / GB;
    int v0 = gb * chunk, v1 = min(v0 + chunk, n);
    {
        int c = 0;
        for (int v = v0 + threadIdx.x; v < v1; v += 1024) {
            int j = __ldcg(&invp[v]);
            c += (min(__ldcg(&hop[j]), 15000) == hstar);
        }
#pragma unroll
        for (int off = 16; off; off >>= 1) c += __shfl_down_sync(0xffffffffu, c, off);
        int wid = threadIdx.x >> 5;
        if (lane == 0) sWarp[wid] = c;
        __syncthreads();
        if (threadIdx.x < 32) {
            int r = sWarp[threadIdx.x];
#pragma unroll
            for (int off = 16; off; off >>= 1) r += __shfl_down_sync(0xffffffffu, r, off);
            if (threadIdx.x == 0) g_blkCntG[g][gb] = r;
        }
    }
    xsync(bar, GB, epoch);
    if (gb == 0) {
        int b = threadIdx.x;
        int v = (b < GB) ? __ldcg(&g_blkCntG[g][b]) : 0;
        int incl = blockScanInc(v, sWarp);
        int excl = incl - v;
        if (b < GB && v > 0 && excl < rrem && rrem <= incl) {
            g_pselBlockG[g] = b; g_pselRemG[g] = rrem - excl;
        }
    }
    xsync(bar, GB, epoch);
    if (gb == *(volatile int*)&g_pselBlockG[g]) {
        int rem = *(volatile int*)&g_pselRemG[g];
        __shared__ int sRun2, sTot2, sDone2;
        if (threadIdx.x == 0) { sRun2 = 0; sDone2 = 0; }
        __syncthreads();
        for (int base = v0; base < v1; base += 1024) {
            if (sDone2) break;
            int v = base + threadIdx.x;
            int pred = 0;
            if (v < v1) {
                int j = __ldcg(&invp[v]);
                pred = (min(__ldcg(&hop[j]), 15000) == hstar);
            }
            int incl = blockScanInc(pred, sWarp);
            int cum = sRun2 + incl;
            if (pred && cum == rem) { g_pstarG[g] = v; sDone2 = 1; }
            if (threadIdx.x == 1023) sTot2 = incl;
            __syncthreads();
            if (threadIdx.x == 0) sRun2 += sTot2;
            __syncthreads();
        }
    }
    xsync(bar, GB, epoch);
    int pstar = *(volatile int*)&g_pstarG[g];
    for (int i = gtid; i < n; i += gsz) {
        int hv = min(__ldcg(&hop[i]), 15000);
        keep[i] = (hv < hstar) || (hv == hstar && __ldg(&perm[i]) <= pstar);
    }
    xexit(bar, GB, epoch);
}

// ============================================================================
// Kernel 3: annotate colD with source keep bits (bit30 = keep1, bit31 = keep2)
// ============================================================================

__global__ __launch_bounds__(1024)
void annotate_kernel(int e) {
    int i = blockIdx.x * 1024 + threadIdx.x;
    int gsz = gridDim.x * 1024;
    for (; i < e; i += gsz) {
        unsigned c = g_colD[i] & 0x3FFFFFFFu;
        unsigned k1 = (unsigned)g_keep1[c];
        unsigned k2 = (unsigned)g_keep2[c];
        g_colD[i] = c | (k1 << 30) | (k2 << 31);
    }
}

// ============================================================================
// Kernel 4: mega GCN — pos+neg+mask1+mask2, annotated colD, 4-edge unroll,
// f32x2 packed GEMV (node-pair lanes), fp16 h output; LAST block computes v.
// ============================================================================

__global__ __launch_bounds__(256)
void mega_gcn_kernel(const float* __restrict__ Wenc, const float* __restrict__ Wdisc,
                     int n, int k) {
    __shared__ float sW[4096];
    __shared__ float sxp[8][64][2];
    __shared__ float sxn[8][64][2];
    __shared__ float sx1[8][64][2];
    __shared__ float sx2[8][64][2];
    __shared__ double sSum[128];
    __shared__ int sLast;
    int tid = threadIdx.x;
    for (int j = tid; j < 4096; j += 256) sW[j] = Wenc[j];
    if (tid < 128) sSum[tid] = 0.0;
    __syncthreads();
    int warp = tid >> 5, lane = tid & 31;
    double A10 = 0.0, A11 = 0.0, A20 = 0.0, A21 = 0.0;
    const __half2* FP = reinterpret_cast<const __half2*>(g_feat16);
    const __half2* FN = reinterpret_cast<const __half2*>(g_featneg16);

    for (int nb = (blockIdx.x * 8 + warp) * 2; nb < n; nb += gridDim.x * 16) {
        int k1d[2], k2d[2];
#pragma unroll
        for (int j = 0; j < 2; j++) {
            int node = nb + j;
            bool valid = node < n;
            k1d[j] = valid ? (int)g_keep1[node] : 0;
            k2d[j] = valid ? (int)g_keep2[node] : 0;
            int s0 = valid ? g_rowD[node] : 0;
            int s1 = valid ? g_rowD[node + 1] : 0;

            float p0 = 0.f, p1 = 0.f, q0 = 0.f, q1 = 0.f;
            float m10 = 0.f, m11 = 0.f, m20 = 0.f, m21 = 0.f;
            int c1 = 0, c2 = 0;

            int e2 = s0;
            for (; e2 + 4 <= s1; e2 += 4) {
                unsigned cA = __ldcs(&g_colD[e2]);
                unsigned cB = __ldcs(&g_colD[e2 + 1]);
                unsigned cC = __ldcs(&g_colD[e2 + 2]);
                unsigned cD = __ldcs(&g_colD[e2 + 3]);
                unsigned sA = cA & 0x3FFFFFFFu, sB = cB & 0x3FFFFFFFu;
                unsigned sC = cC & 0x3FFFFFFFu, sD = cD & 0x3FFFFFFFu;
                float2 fA = __half22float2(FP[(size_t)sA * 32 + lane]);
                float2 fB = __half22float2(FP[(size_t)sB * 32 + lane]);
                float2 fC = __half22float2(FP[(size_t)sC * 32 + lane]);
                float2 fD = __half22float2(FP[(size_t)sD * 32 + lane]);
                float2 gA = __half22float2(FN[(size_t)sA * 32 + lane]);
                float2 gB2 = __half22float2(FN[(size_t)sB * 32 + lane]);
                float2 gC = __half22float2(FN[(size_t)sC * 32 + lane]);
                float2 gD = __half22float2(FN[(size_t)sD * 32 + lane]);
                p0 += (fA.x + fB.x) + (fC.x + fD.x);
                p1 += (fA.y + fB.y) + (fC.y + fD.y);
                q0 += (gA.x + gB2.x) + (gC.x + gD.x);
                q1 += (gA.y + gB2.y) + (gC.y + gD.y);
                int kA1 = (int)(cA >> 30) & 1 & k1d[j], kB1 = (int)(cB >> 30) & 1 & k1d[j];
                int kC1 = (int)(cC >> 30) & 1 & k1d[j], kD1 = (int)(cD >> 30) & 1 & k1d[j];
                int kA2 = (int)(cA >> 31) & k2d[j], kB2 = (int)(cB >> 31) & k2d[j];
                int kC2 = (int)(cC >> 31) & k2d[j], kD2 = (int)(cD >> 31) & k2d[j];
                m10 += fA.x * (float)kA1 + fB.x * (float)kB1 + fC.x * (float)kC1 + fD.x * (float)kD1;
                m11 += fA.y * (float)kA1 + fB.y * (float)kB1 + fC.y * (float)kC1 + fD.y * (float)kD1;
                m20 += fA.x * (float)kA2 + fB.x * (float)kB2 + fC.x * (float)kC2 + fD.x * (float)kD2;
                m21 += fA.y * (float)kA2 + fB.y * (float)kB2 + fC.y * (float)kC2 + fD.y * (float)kD2;
                c1 += kA1 + kB1 + kC1 + kD1;
                c2 += kA2 + kB2 + kC2 + kD2;
            }
            for (; e2 < s1; e2++) {
                unsigned cA = __ldcs(&g_colD[e2]);
                unsigned sA = cA & 0x3FFFFFFFu;
                float2 fA = __half22float2(FP[(size_t)sA * 32 + lane]);
                float2 gA = __half22float2(FN[(size_t)sA * 32 + lane]);
                p0 += fA.x; p1 += fA.y; q0 += gA.x; q1 += gA.y;
                int kA1 = (int)(cA >> 30) & 1 & k1d[j];
                int kA2 = (int)(cA >> 31) & k2d[j];
                m10 += fA.x * (float)kA1; m11 += fA.y * (float)kA1;
                m20 += fA.x * (float)kA2; m21 += fA.y * (float)kA2;
                c1 += kA1; c2 += kA2;
            }

            float invd = 1.f / (float)max(s1 - s0, 1);
            float i1 = 1.f / (float)max(c1, 1);
            float i2 = 1.f / (float)max(c2, 1);
            sxp[warp][2 * lane][j] = p0 * invd; sxp[warp][2 * lane + 1][j] = p1 * invd;
            sxn[warp][2 * lane][j] = q0 * invd; sxn[warp][2 * lane + 1][j] = q1 * invd;
            sx1[warp][2 * lane][j] = m10 * i1;  sx1[warp][2 * lane + 1][j] = m11 * i1;
            sx2[warp][2 * lane][j] = m20 * i2;  sx2[warp][2 * lane + 1][j] = m21 * i2;
        }
        __syncwarp();

        // f32x2 packed GEMV: each ull accumulator = (node0, node1)
        ull oPa = 0, oPb = 0, oNa = 0, oNb = 0;
        ull o1a = 0, o1b = 0, o2a = 0, o2b = 0;
#pragma unroll 16
        for (int kk = 0; kk < 64; kk++) {
            float2 w = *reinterpret_cast<const float2*>(&sW[kk * 64 + 2 * lane]);
            ull wa = pack2(w.x, w.x);
            ull wb = pack2(w.y, w.y);
            ull xp = *reinterpret_cast<const ull*>(&sxp[warp][kk][0]);
            ull xn = *reinterpret_cast<const ull*>(&sxn[warp][kk][0]);
            ull x1 = *reinterpret_cast<const ull*>(&sx1[warp][kk][0]);
            ull x2 = *reinterpret_cast<const ull*>(&sx2[warp][kk][0]);
            oPa = fma2(xp, wa, oPa); oPb = fma2(xp, wb, oPb);
            oNa = fma2(xn, wa, oNa); oNb = fma2(xn, wb, oNb);
            o1a = fma2(x1, wa, o1a); o1b = fma2(x1, wb, o1b);
            o2a = fma2(x2, wa, o2a); o2b = fma2(x2, wb, o2b);
        }
        float opa[2], opb[2], ona[2], onb[2], m1a[2], m1b[2], m2a[2], m2b[2];
        unpack2(oPa, opa[0], opa[1]); unpack2(oPb, opb[0], opb[1]);
        unpack2(oNa, ona[0], ona[1]); unpack2(oNb, onb[0], onb[1]);
        unpack2(o1a, m1a[0], m1a[1]); unpack2(o1b, m1b[0], m1b[1]);
        unpack2(o2a, m2a[0], m2a[1]); unpack2(o2b, m2b[0], m2b[1]);
#pragma unroll
        for (int j = 0; j < 2; j++) {
            int node = nb + j;
            if (node < n) {
                reinterpret_cast<__half2*>(g_hpos16)[(size_t)node * 32 + lane] =
                    __floats2half2_rn(fmaxf(opa[j], 0.f), fmaxf(opb[j], 0.f));
                reinterpret_cast<__half2*>(g_hneg16)[(size_t)node * 32 + lane] =
                    __floats2half2_rn(fmaxf(ona[j], 0.f), fmaxf(onb[j], 0.f));
                if (k1d[j]) { A10 += (double)fmaxf(m1a[j], 0.f); A11 += (double)fmaxf(m1b[j], 0.f); }
                if (k2d[j]) { A20 += (double)fmaxf(m2a[j], 0.f); A21 += (double)fmaxf(m2b[j], 0.f); }
            }
        }
        __syncwarp();
    }
    atomicAdd(&sSum[2 * lane], A10);
    atomicAdd(&sSum[2 * lane + 1], A11);
    atomicAdd(&sSum[64 + 2 * lane], A20);
    atomicAdd(&sSum[64 + 2 * lane + 1], A21);
    __syncthreads();
    if (tid < 128) {
        double v = sSum[tid];
        if (v != 0.0) atomicAdd(&g_summary[tid], v);
    }

    if (tid == 0) {
        __threadfence();
        sLast = (atomicAdd(&g_ctrMega, 1u) == gridDim.x - 1);
    }
    __syncthreads();
    if (sLast) {
        __shared__ float ss[2][64];
        if (tid < 128) {
            double s = g_summary[tid] / (double)k;
            ss[tid >> 6][tid & 63] = (float)(1.0 / (1.0 + exp(-s)));
        }
        __syncthreads();
        if (tid < 128) {
            int p = tid >> 6, c = tid & 63;
            float v = 0.f;
#pragma unroll
            for (int b = 0; b < 64; b++) v += Wdisc[c * 64 + b] * ss[p][b];
            g_v[p][c] = v;
        }
        if (tid == 0) g_ctrMega = 0;
    }
}

// ============================================================================
// Kernel 5: BCE losses (streams fp16 h); last block writes final output.
// ============================================================================

__global__ __launch_bounds__(256)
void loss_kernel(float* __restrict__ out, int n) {
    __shared__ float sv0[64], sv1[64];
    __shared__ double sL[4];
    __shared__ int sLast;
    int tid = threadIdx.x;
    if (tid < 64) { sv0[tid] = g_v[0][tid]; sv1[tid] = g_v[1][tid]; }
    if (tid < 4) sL[tid] = 0.0;
    __syncthreads();
    int warp = tid >> 5, lane = tid & 31;
    float v00 = sv0[2 * lane], v01 = sv0[2 * lane + 1];
    float v10 = sv1[2 * lane], v11 = sv1[2 * lane + 1];
    double l0 = 0, l1 = 0, l2 = 0, l3 = 0;
    const __half2* HP = reinterpret_cast<const __half2*>(g_hpos16);
    const __half2* HN = reinterpret_cast<const __half2*>(g_hneg16);
    for (int node = blockIdx.x * 8 + warp; node < n; node += gridDim.x * 8) {
        float2 hp = __half22float2(HP[(size_t)node * 32 + lane]);
        float2 hn = __half22float2(HN[(size_t)node * 32 + lane]);
        float p1 = hp.x * v00 + hp.y * v01;
        float p2 = hp.x * v10 + hp.y * v11;
        float q1 = hn.x * v00 + hn.y * v01;
        float q2 = hn.x * v10 + hn.y * v11;
#pragma unroll
        for (int off = 16; off; off >>= 1) {
            p1 += __shfl_down_sync(0xffffffffu, p1, off);
            p2 += __shfl_down_sync(0xffffffffu, p2, off);
            q1 += __shfl_down_sync(0xffffffffu, q1, off);
            q2 += __shfl_down_sync(0xffffffffu, q2, off);
        }
        if (lane == 0) {
            l0 += (double)softplusf(-p1);
            l1 += (double)softplusf(q1);
            l2 += (double)softplusf(-p2);
            l3 += (double)softplusf(q2);
        }
    }
    if (lane == 0) {
        atomicAdd(&sL[0], l0); atomicAdd(&sL[1], l1);
        atomicAdd(&sL[2], l2); atomicAdd(&sL[3], l3);
    }
    __syncthreads();
    if (tid < 4) atomicAdd(&g_loss[tid], sL[tid]);

    if (tid == 0) {
        __threadfence();
        sLast = (atomicAdd(&g_ctrLoss, 1u) == gridDim.x - 1);
    }
    __syncthreads();
    if (sLast && tid == 0) {
        out[0] = (float)((g_loss[0] + g_loss[1] + g_loss[2] + g_loss[3]) / (double)n);
        g_ctrLoss = 0;
    }
}

// ============================================================================
// launch
// ============================================================================

extern "C" void kernel_launch(void* const* d_in, const int* in_sizes, int n_in,
                              void* d_out, int out_size) {
    const float* feat = (const float*)d_in[0];
    const float* Wenc = (const float*)d_in[1];
    const float* Wdisc = (const float*)d_in[2];
    const int* src = (const int*)d_in[3];
    const int* dst = (const int*)d_in[4];
    const int* permneg = (const int*)d_in[5];
    const int* perm1 = (const int*)d_in[6];
    const int* perm2 = (const int*)d_in[7];

    int e = in_sizes[3];
    int n = in_sizes[5];
    int k = (int)((double)n * 0.8);

    csr_kernel<<<CSRB, 1024>>>(feat, src, dst, permneg, e, n);
    bfs_dual_kernel<<<BFSB, 1024>>>(perm1, perm2, n, k);
    annotate_kernel<<<264, 1024>>>(e);

    int mGrid = (n + 15) / 16;
    if (mGrid > 1480) mGrid = 1480;
    mega_gcn_kernel<<<mGrid, 256>>>(Wenc, Wdisc, n, k);

    int lGrid = (n + 7) / 8;
    if (lGrid > 1480) lGrid = 1480;
    loss_kernel<<<lGrid, 256>>>((float*)d_out, n);
}